// round 5
// baseline (speedup 1.0000x reference)
#include <cuda_runtime.h>
#include <math.h>
#include <stdint.h>

// Problem dims
#define BD   2
#define TD   2048
#define CD   1024
#define HN   16
#define HD   64
#define DFFD 4096
#define NT   (BD * TD)   // 4096 tokens

// ---------------------------------------------------------------------------
// Scratch
// ---------------------------------------------------------------------------
__device__ float g_t  [(size_t)NT * CD];
__device__ float g_q  [(size_t)NT * CD];
__device__ float g_k  [(size_t)NT * CD];
__device__ float g_v  [(size_t)NT * CD];
__device__ float g_ctx[(size_t)NT * CD];
__device__ float g_x2 [(size_t)NT * CD];
__device__ float g_h  [(size_t)NT * DFFD];

// ---------------------------------------------------------------------------
// Helpers
// ---------------------------------------------------------------------------
__device__ __forceinline__ uint32_t f2tf32(float f) {
    uint32_t u;
    asm("cvt.rna.tf32.f32 %0, %1;" : "=r"(u) : "f"(f));
    return u;
}
__device__ __forceinline__ void cp16(uint32_t smem_dst, const void* gptr) {
    asm volatile("cp.async.cg.shared.global [%0], [%1], 16;\n"
                 :: "r"(smem_dst), "l"(gptr));
}
__device__ __forceinline__ void cp_commit() {
    asm volatile("cp.async.commit_group;\n" ::: "memory");
}
template <int N>
__device__ __forceinline__ void cp_wait() {
    asm volatile("cp.async.wait_group %0;\n" :: "n"(N) : "memory");
}
__device__ __forceinline__ void mma_tf32(float* c, const uint32_t* a, const uint32_t* b) {
    asm volatile(
        "mma.sync.aligned.m16n8k8.row.col.f32.tf32.tf32.f32 "
        "{%0,%1,%2,%3},{%4,%5,%6,%7},{%8,%9},{%0,%1,%2,%3};"
        : "+f"(c[0]), "+f"(c[1]), "+f"(c[2]), "+f"(c[3])
        : "r"(a[0]), "r"(a[1]), "r"(a[2]), "r"(a[3]), "r"(b[0]), "r"(b[1]));
}

// ---------------------------------------------------------------------------
// Fused double LayerNorm
// ---------------------------------------------------------------------------
__global__ __launch_bounds__(256) void ln2_kernel(
    const float* __restrict__ x,
    const float* __restrict__ ga, const float* __restrict__ ba,
    const float* __restrict__ gb, const float* __restrict__ bb,
    float* __restrict__ out)
{
    __shared__ float red[16];
    __shared__ float bc[2];
    const int row = blockIdx.x, tid = threadIdx.x;
    const float4 v = *(const float4*)(x + (size_t)row * CD + tid * 4);

    float s  = v.x + v.y + v.z + v.w;
    float s2 = v.x*v.x + v.y*v.y + v.z*v.z + v.w*v.w;
    #pragma unroll
    for (int o = 16; o; o >>= 1) {
        s  += __shfl_xor_sync(~0u, s,  o);
        s2 += __shfl_xor_sync(~0u, s2, o);
    }
    if ((tid & 31) == 0) { red[(tid >> 5)*2] = s; red[(tid >> 5)*2 + 1] = s2; }
    __syncthreads();
    if (tid == 0) {
        float a = 0.f, b2 = 0.f;
        #pragma unroll
        for (int w = 0; w < 8; w++) { a += red[w*2]; b2 += red[w*2 + 1]; }
        float mu  = a * (1.f / CD);
        float var = b2 * (1.f / CD) - mu * mu;
        bc[0] = mu; bc[1] = rsqrtf(var + 1e-5f);
    }
    __syncthreads();
    float mu = bc[0], rstd = bc[1];
    __syncthreads();

    const float4 g4 = *(const float4*)(ga + tid * 4);
    const float4 b4 = *(const float4*)(ba + tid * 4);
    float y[4];
    y[0] = (v.x - mu) * rstd * g4.x + b4.x;
    y[1] = (v.y - mu) * rstd * g4.y + b4.y;
    y[2] = (v.z - mu) * rstd * g4.z + b4.z;
    y[3] = (v.w - mu) * rstd * g4.w + b4.w;

    s  = y[0] + y[1] + y[2] + y[3];
    s2 = y[0]*y[0] + y[1]*y[1] + y[2]*y[2] + y[3]*y[3];
    #pragma unroll
    for (int o = 16; o; o >>= 1) {
        s  += __shfl_xor_sync(~0u, s,  o);
        s2 += __shfl_xor_sync(~0u, s2, o);
    }
    if ((tid & 31) == 0) { red[(tid >> 5)*2] = s; red[(tid >> 5)*2 + 1] = s2; }
    __syncthreads();
    if (tid == 0) {
        float a = 0.f, b2 = 0.f;
        #pragma unroll
        for (int w = 0; w < 8; w++) { a += red[w*2]; b2 += red[w*2 + 1]; }
        float mu2  = a * (1.f / CD);
        float var2 = b2 * (1.f / CD) - mu2 * mu2;
        bc[0] = mu2; bc[1] = rsqrtf(var2 + 1e-5f);
    }
    __syncthreads();
    mu = bc[0]; rstd = bc[1];

    const float4 g24 = *(const float4*)(gb + tid * 4);
    const float4 b24 = *(const float4*)(bb + tid * 4);
    float4 o;
    o.x = (y[0] - mu) * rstd * g24.x + b24.x;
    o.y = (y[1] - mu) * rstd * g24.y + b24.y;
    o.z = (y[2] - mu) * rstd * g24.z + b24.z;
    o.w = (y[3] - mu) * rstd * g24.w + b24.w;
    *(float4*)(out + (size_t)row * CD + tid * 4) = o;
}

__global__ __launch_bounds__(256) void ln1_kernel(
    const float* __restrict__ x,
    const float* __restrict__ g, const float* __restrict__ b,
    float* __restrict__ out)
{
    __shared__ float red[16];
    __shared__ float bc[2];
    const int row = blockIdx.x, tid = threadIdx.x;
    const float4 v = *(const float4*)(x + (size_t)row * CD + tid * 4);

    float s  = v.x + v.y + v.z + v.w;
    float s2 = v.x*v.x + v.y*v.y + v.z*v.z + v.w*v.w;
    #pragma unroll
    for (int o = 16; o; o >>= 1) {
        s  += __shfl_xor_sync(~0u, s,  o);
        s2 += __shfl_xor_sync(~0u, s2, o);
    }
    if ((tid & 31) == 0) { red[(tid >> 5)*2] = s; red[(tid >> 5)*2 + 1] = s2; }
    __syncthreads();
    if (tid == 0) {
        float a = 0.f, b2 = 0.f;
        #pragma unroll
        for (int w = 0; w < 8; w++) { a += red[w*2]; b2 += red[w*2 + 1]; }
        float mu  = a * (1.f / CD);
        float var = b2 * (1.f / CD) - mu * mu;
        bc[0] = mu; bc[1] = rsqrtf(var + 1e-5f);
    }
    __syncthreads();
    const float mu = bc[0], rstd = bc[1];
    const float4 g4 = *(const float4*)(g + tid * 4);
    const float4 b4 = *(const float4*)(b + tid * 4);
    float4 o;
    o.x = (v.x - mu) * rstd * g4.x + b4.x;
    o.y = (v.y - mu) * rstd * g4.y + b4.y;
    o.z = (v.z - mu) * rstd * g4.z + b4.z;
    o.w = (v.w - mu) * rstd * g4.w + b4.w;
    *(float4*)(out + (size_t)row * CD + tid * 4) = o;
}

// ---------------------------------------------------------------------------
// TF32 tensor-core GEMM v3: 128x128 tile, BK=16, 8 warps (2x4), warp 64x32,
// 4-stage cp.async ring, ONE syncthreads per k-tile. cvt.rna on A only.
//   A smem: [m][k'] k' = k ^ (4*((m>>1)&3)), row stride 16
//   B smem: [k][n'] n' = n ^ (8*k),          row stride 128
// Dynamic smem: 4 stages x (2048 + 2048) floats = 64 KB.
// ---------------------------------------------------------------------------
#define GSTG 4
#define GEMM_SMEM (GSTG * 4096 * 2 * 4)

__global__ __launch_bounds__(256, 2) void gemm_tc(
    const float* __restrict__ A, const float* __restrict__ W,
    const float* __restrict__ bias, const float* __restrict__ res,
    float* __restrict__ Cc, int M, int N, int K, int act)
{
    extern __shared__ float gsm[];
    float* Asm = gsm;                    // [GSTG][2048]
    float* Bsm = gsm + GSTG * 2048;      // [GSTG][2048]

    const int tid  = threadIdx.x;
    const int lane = tid & 31;
    const int warp = tid >> 5;
    const int wm = warp & 1;
    const int wn = warp >> 1;
    const int bm = blockIdx.y * 128;
    const int bn = blockIdx.x * 128;

    const uint32_t sA = (uint32_t)__cvta_generic_to_shared(Asm);
    const uint32_t sB = (uint32_t)__cvta_generic_to_shared(Bsm);

    const int am  = (tid + 0)   >> 2,  ak  = (tid + 0)   & 3;
    const int am2 = (tid + 256) >> 2,  ak2 = (tid + 256) & 3;
    const int bk  = (tid + 0)   >> 5,  bn4 = (tid + 0)   & 31;
    const int bk2 = (tid + 256) >> 5,  bn42= (tid + 256) & 31;

    float acc[4][4][4];
    #pragma unroll
    for (int i = 0; i < 4; i++)
        #pragma unroll
        for (int j = 0; j < 4; j++)
            #pragma unroll
            for (int r = 0; r < 4; r++) acc[i][j][r] = 0.f;

    auto issue = [&](int s, int k0) {
        uint32_t d = sA + (uint32_t)(s * 2048 + am * 16 + ((ak * 4) ^ (4 * ((am >> 1) & 3)))) * 4u;
        cp16(d, A + (size_t)(bm + am) * K + k0 + ak * 4);
        uint32_t d2 = sA + (uint32_t)(s * 2048 + am2 * 16 + ((ak2 * 4) ^ (4 * ((am2 >> 1) & 3)))) * 4u;
        cp16(d2, A + (size_t)(bm + am2) * K + k0 + ak2 * 4);
        uint32_t e = sB + (uint32_t)(s * 2048 + bk * 128 + ((bn4 * 4) ^ (8 * bk))) * 4u;
        cp16(e, W + (size_t)(k0 + bk) * N + bn + bn4 * 4);
        uint32_t e2 = sB + (uint32_t)(s * 2048 + bk2 * 128 + ((bn42 * 4) ^ (8 * bk2))) * 4u;
        cp16(e2, W + (size_t)(k0 + bk2) * N + bn + bn42 * 4);
    };

    issue(0, 0);  cp_commit();
    issue(1, 16); cp_commit();
    issue(2, 32); cp_commit();

    const int nK = K >> 4;
    const int r4 = lane >> 2;
    const int c4 = lane & 3;

    for (int kt = 0; kt < nK; kt++) {
        cp_wait<2>();
        __syncthreads();
        // refill the slot freed at iteration kt-1 (all warps are past it)
        const int knext = (kt + 3) << 4;
        if (knext < K) issue((kt + 3) & (GSTG - 1), knext);
        cp_commit();

        const int cur = kt & (GSTG - 1);
        const float* Ap = Asm + cur * 2048;
        const float* Bp = Bsm + cur * 2048;

        #pragma unroll
        for (int k8 = 0; k8 < 2; k8++) {
            const int kb = k8 * 8 + c4;
            uint32_t af[4][4], bf[4][2];
            #pragma unroll
            for (int mf = 0; mf < 4; mf++) {
                const int m0 = wm * 64 + mf * 16 + r4;
                const int xm = 4 * ((m0 >> 1) & 3);
                const float* p = Ap + m0 * 16;
                af[mf][0] = f2tf32(p[kb ^ xm]);
                af[mf][1] = f2tf32(p[128 + (kb ^ xm)]);
                af[mf][2] = f2tf32(p[(kb + 4) ^ xm]);
                af[mf][3] = f2tf32(p[128 + ((kb + 4) ^ xm)]);
            }
            #pragma unroll
            for (int nf = 0; nf < 4; nf++) {
                const int n = wn * 32 + nf * 8 + r4;
                bf[nf][0] = __float_as_uint(Bp[kb * 128 + (n ^ (8 * kb))]);
                bf[nf][1] = __float_as_uint(Bp[(kb + 4) * 128 + (n ^ (8 * (kb + 4)))]);
            }
            #pragma unroll
            for (int mf = 0; mf < 4; mf++)
                #pragma unroll
                for (int nf = 0; nf < 4; nf++)
                    mma_tf32(acc[mf][nf], af[mf], bf[nf]);
        }
    }

    // epilogue
    #pragma unroll
    for (int mf = 0; mf < 4; mf++) {
        #pragma unroll
        for (int nf = 0; nf < 4; nf++) {
            const int col = bn + wn * 32 + nf * 8 + c4 * 2;
            const float bx = bias[col], by = bias[col + 1];
            #pragma unroll
            for (int h = 0; h < 2; h++) {
                const int row = bm + wm * 64 + mf * 16 + r4 + h * 8;
                float ox = acc[mf][nf][h * 2 + 0] + bx;
                float oy = acc[mf][nf][h * 2 + 1] + by;
                if (act) {
                    ox *= 1.f / (1.f + __expf(-ox));
                    oy *= 1.f / (1.f + __expf(-oy));
                }
                const size_t off = (size_t)row * N + col;
                if (res) {
                    const float2 rr = *(const float2*)(res + off);
                    ox += rr.x; oy += rr.y;
                }
                float2 o; o.x = ox; o.y = oy;
                *(float2*)(Cc + off) = o;
            }
        }
    }
}

// ---------------------------------------------------------------------------
// Flash attention on tensor cores (unchanged from R3)
// ---------------------------------------------------------------------------
#define PQ 68
#define PV 72
#define ATTN_SMEM ((64*PQ + 2*64*PQ + 2*64*PV + 4*16*PQ) * 4)

__global__ __launch_bounds__(128) void attn_tc(
    const float* __restrict__ Q, const float* __restrict__ Kg,
    const float* __restrict__ Vg, float* __restrict__ O)
{
    extern __shared__ float sm[];
    float* Qs = sm;
    float* Ks = Qs + 64 * PQ;
    float* Vs = Ks + 2 * 64 * PQ;
    float* Ps = Vs + 2 * 64 * PV;

    const int bh = blockIdx.y;
    const int b = bh >> 4, h = bh & 15;
    const int qt = blockIdx.x;
    const int q0 = qt * 64;
    const int tid = threadIdx.x;
    const int lane = tid & 31;
    const int warp = tid >> 5;
    const int r4 = lane >> 2;
    const int c4 = lane & 3;
    const size_t base = (size_t)b * TD * CD + (size_t)h * HD;

    const uint32_t sQ = (uint32_t)__cvta_generic_to_shared(Qs);
    const uint32_t sK = (uint32_t)__cvta_generic_to_shared(Ks);
    const uint32_t sV = (uint32_t)__cvta_generic_to_shared(Vs);

    #pragma unroll
    for (int i = 0; i < 8; i++) {
        const int idx = tid + i * 128;
        const int row = idx >> 4, cc = idx & 15;
        cp16(sQ + (uint32_t)(row * PQ + cc * 4) * 4u,
             Q + base + (size_t)(q0 + row) * CD + cc * 4);
    }
    auto issue_kv = [&](int buf, int k0) {
        #pragma unroll
        for (int i = 0; i < 8; i++) {
            const int idx = tid + i * 128;
            const int row = idx >> 4, cc = idx & 15;
            const size_t g = base + (size_t)(k0 + row) * CD + cc * 4;
            cp16(sK + (uint32_t)(buf * 64 * PQ + row * PQ + cc * 4) * 4u, Kg + g);
            cp16(sV + (uint32_t)(buf * 64 * PV + row * PV + cc * 4) * 4u, Vg + g);
        }
    };
    issue_kv(0, 0);
    cp_commit();
    if (qt >= 1) { issue_kv(1, 64); cp_commit(); }

    uint32_t qf[8][4];
    float oacc[8][4];
    #pragma unroll
    for (int nt = 0; nt < 8; nt++)
        #pragma unroll
        for (int r = 0; r < 4; r++) oacc[nt][r] = 0.f;
    float m0 = -1e30f, m1 = -1e30f, l0 = 0.f, l1 = 0.f;

    float* Pw = Ps + warp * 16 * PQ;

    for (int kt = 0; kt <= qt; kt++) {
        if (kt + 1 <= qt) cp_wait<1>(); else cp_wait<0>();
        __syncthreads();
        const int cur = kt & 1;
        const float* Kp = Ks + cur * 64 * PQ;
        const float* Vp = Vs + cur * 64 * PV;

        if (kt == 0) {
            const float* qp = Qs + (warp * 16 + r4) * PQ;
            #pragma unroll
            for (int ks = 0; ks < 8; ks++) {
                const int c = ks * 8 + c4;
                qf[ks][0] = __float_as_uint(qp[c] * 0.125f);
                qf[ks][1] = __float_as_uint(qp[8 * PQ + c] * 0.125f);
                qf[ks][2] = __float_as_uint(qp[c + 4] * 0.125f);
                qf[ks][3] = __float_as_uint(qp[8 * PQ + c + 4] * 0.125f);
            }
        }

        float sacc[8][4];
        #pragma unroll
        for (int nt = 0; nt < 8; nt++)
            #pragma unroll
            for (int r = 0; r < 4; r++) sacc[nt][r] = 0.f;

        #pragma unroll
        for (int ks = 0; ks < 8; ks++) {
            const int k = ks * 8 + c4;
            #pragma unroll
            for (int nt = 0; nt < 8; nt++) {
                const int n = nt * 8 + r4;
                uint32_t bf[2];
                bf[0] = __float_as_uint(Kp[n * PQ + k]);
                bf[1] = __float_as_uint(Kp[n * PQ + k + 4]);
                mma_tf32(sacc[nt], qf[ks], bf);
            }
        }

        if (kt == qt) {
            const int row0 = warp * 16 + r4;
            #pragma unroll
            for (int nt = 0; nt < 8; nt++) {
                const int cb = nt * 8 + 2 * c4;
                if (cb + 0 > row0)     sacc[nt][0] = -1e30f;
                if (cb + 1 > row0)     sacc[nt][1] = -1e30f;
                if (cb + 0 > row0 + 8) sacc[nt][2] = -1e30f;
                if (cb + 1 > row0 + 8) sacc[nt][3] = -1e30f;
            }
        }

        float rm0 = -1e30f, rm1 = -1e30f;
        #pragma unroll
        for (int nt = 0; nt < 8; nt++) {
            rm0 = fmaxf(rm0, fmaxf(sacc[nt][0], sacc[nt][1]));
            rm1 = fmaxf(rm1, fmaxf(sacc[nt][2], sacc[nt][3]));
        }
        rm0 = fmaxf(rm0, __shfl_xor_sync(~0u, rm0, 1));
        rm0 = fmaxf(rm0, __shfl_xor_sync(~0u, rm0, 2));
        rm1 = fmaxf(rm1, __shfl_xor_sync(~0u, rm1, 1));
        rm1 = fmaxf(rm1, __shfl_xor_sync(~0u, rm1, 2));

        const float mn0 = fmaxf(m0, rm0), mn1 = fmaxf(m1, rm1);
        const float f0 = __expf(m0 - mn0), f1 = __expf(m1 - mn1);
        m0 = mn0; m1 = mn1;

        float rs0 = 0.f, rs1 = 0.f;
        #pragma unroll
        for (int nt = 0; nt < 8; nt++) {
            float p0 = __expf(sacc[nt][0] - mn0);
            float p1 = __expf(sacc[nt][1] - mn0);
            float p2 = __expf(sacc[nt][2] - mn1);
            float p3 = __expf(sacc[nt][3] - mn1);
            rs0 += p0 + p1; rs1 += p2 + p3;
            float2 w0; w0.x = p0; w0.y = p1;
            float2 w1; w1.x = p2; w1.y = p3;
            *(float2*)(Pw + r4 * PQ + nt * 8 + 2 * c4)       = w0;
            *(float2*)(Pw + (r4 + 8) * PQ + nt * 8 + 2 * c4) = w1;
        }
        rs0 += __shfl_xor_sync(~0u, rs0, 1);
        rs0 += __shfl_xor_sync(~0u, rs0, 2);
        rs1 += __shfl_xor_sync(~0u, rs1, 1);
        rs1 += __shfl_xor_sync(~0u, rs1, 2);
        l0 = l0 * f0 + rs0;
        l1 = l1 * f1 + rs1;

        #pragma unroll
        for (int nt = 0; nt < 8; nt++) {
            oacc[nt][0] *= f0; oacc[nt][1] *= f0;
            oacc[nt][2] *= f1; oacc[nt][3] *= f1;
        }
        __syncwarp();

        #pragma unroll
        for (int ks = 0; ks < 8; ks++) {
            const int c = ks * 8 + c4;
            uint32_t af[4];
            af[0] = __float_as_uint(Pw[r4 * PQ + c]);
            af[1] = __float_as_uint(Pw[(r4 + 8) * PQ + c]);
            af[2] = __float_as_uint(Pw[r4 * PQ + c + 4]);
            af[3] = __float_as_uint(Pw[(r4 + 8) * PQ + c + 4]);
            #pragma unroll
            for (int nt = 0; nt < 8; nt++) {
                const int n = nt * 8 + r4;
                uint32_t bf[2];
                bf[0] = __float_as_uint(Vp[c * PV + n]);
                bf[1] = __float_as_uint(Vp[(c + 4) * PV + n]);
                mma_tf32(oacc[nt], af, bf);
            }
        }

        __syncthreads();
        if (kt + 2 <= qt) { issue_kv(cur, (kt + 2) * 64); cp_commit(); }
    }

    const float inv0 = 1.f / l0, inv1 = 1.f / l1;
    const int row0 = q0 + warp * 16 + r4;
    #pragma unroll
    for (int nt = 0; nt < 8; nt++) {
        const int col = h * HD + nt * 8 + 2 * c4;
        float2 o0, o1;
        o0.x = oacc[nt][0] * inv0; o0.y = oacc[nt][1] * inv0;
        o1.x = oacc[nt][2] * inv1; o1.y = oacc[nt][3] * inv1;
        *(float2*)(O + (size_t)(b * TD + row0) * CD + col)     = o0;
        *(float2*)(O + (size_t)(b * TD + row0 + 8) * CD + col) = o1;
    }
}

// ---------------------------------------------------------------------------
// Launch
// ---------------------------------------------------------------------------
extern "C" void kernel_launch(void* const* d_in, const int* in_sizes, int n_in,
                              void* d_out, int out_size)
{
    const float* x      = (const float*)d_in[0];
    const float* ln_a_g = (const float*)d_in[1];
    const float* ln_a_b = (const float*)d_in[2];
    const float* ln_b_g = (const float*)d_in[3];
    const float* ln_b_b = (const float*)d_in[4];
    const float* ln_c_g = (const float*)d_in[5];
    const float* ln_c_b = (const float*)d_in[6];
    const float* Wq = (const float*)d_in[7];  const float* bq = (const float*)d_in[8];
    const float* Wk = (const float*)d_in[9];  const float* bk = (const float*)d_in[10];
    const float* Wv = (const float*)d_in[11]; const float* bv = (const float*)d_in[12];
    const float* Wo = (const float*)d_in[13]; const float* bo = (const float*)d_in[14];
    const float* We = (const float*)d_in[15]; const float* be = (const float*)d_in[16];
    const float* Wd = (const float*)d_in[17]; const float* bd = (const float*)d_in[18];
    float* out = (float*)d_out;

    float *t, *q, *k, *v, *ctx, *x2, *h;
    cudaGetSymbolAddress((void**)&t,   g_t);
    cudaGetSymbolAddress((void**)&q,   g_q);
    cudaGetSymbolAddress((void**)&k,   g_k);
    cudaGetSymbolAddress((void**)&v,   g_v);
    cudaGetSymbolAddress((void**)&ctx, g_ctx);
    cudaGetSymbolAddress((void**)&x2,  g_x2);
    cudaGetSymbolAddress((void**)&h,   g_h);

    cudaFuncSetAttribute(attn_tc, cudaFuncAttributeMaxDynamicSharedMemorySize,
                         ATTN_SMEM);
    cudaFuncSetAttribute(gemm_tc, cudaFuncAttributeMaxDynamicSharedMemorySize,
                         GEMM_SMEM);

    // 1. t = LN_b(LN_a(x))
    ln2_kernel<<<NT, 256>>>(x, ln_a_g, ln_a_b, ln_b_g, ln_b_b, t);

    // 2. QKV projections
    {
        dim3 grid(CD / 128, NT / 128);
        gemm_tc<<<grid, 256, GEMM_SMEM>>>(t, Wq, bq, nullptr, q, NT, CD, CD, 0);
        gemm_tc<<<grid, 256, GEMM_SMEM>>>(t, Wk, bk, nullptr, k, NT, CD, CD, 0);
        gemm_tc<<<grid, 256, GEMM_SMEM>>>(t, Wv, bv, nullptr, v, NT, CD, CD, 0);
    }

    // 3. causal attention
    {
        dim3 grid(TD / 64, BD * HN);
        attn_tc<<<grid, 128, ATTN_SMEM>>>(q, k, v, ctx);
    }

    // 4. x2 = x + ctx @ Wo + bo
    {
        dim3 grid(CD / 128, NT / 128);
        gemm_tc<<<grid, 256, GEMM_SMEM>>>(ctx, Wo, bo, x, x2, NT, CD, CD, 0);
    }

    // 5. t = LN_c(x2)
    ln1_kernel<<<NT, 256>>>(x2, ln_c_g, ln_c_b, t);

    // 6. h = silu(t @ We + be)
    {
        dim3 grid(DFFD / 128, NT / 128);
        gemm_tc<<<grid, 256, GEMM_SMEM>>>(t, We, be, nullptr, h, NT, DFFD, CD, 1);
    }

    // 7. out = x2 + h @ Wd + bd
    {
        dim3 grid(CD / 128, NT / 128);
        gemm_tc<<<grid, 256, GEMM_SMEM>>>(h, Wd, bd, x2, out, NT, CD, DFFD, 0);
    }
}

// round 6
// speedup vs baseline: 1.1425x; 1.1425x over previous
#include <cuda_runtime.h>
#include <math.h>
#include <stdint.h>

// Problem dims
#define BD   2
#define TD   2048
#define CD   1024
#define HN   16
#define HD   64
#define DFFD 4096
#define NT   (BD * TD)   // 4096 tokens

// ---------------------------------------------------------------------------
// Scratch
// ---------------------------------------------------------------------------
__device__ float g_t  [(size_t)NT * CD];
__device__ float g_q  [(size_t)NT * CD];
__device__ float g_k  [(size_t)NT * CD];
__device__ float g_v  [(size_t)NT * CD];
__device__ float g_ctx[(size_t)NT * CD];
__device__ float g_x2 [(size_t)NT * CD];
__device__ float g_h  [(size_t)NT * DFFD];

// ---------------------------------------------------------------------------
// Helpers
// ---------------------------------------------------------------------------
__device__ __forceinline__ uint32_t f2tf32(float f) {
    uint32_t u;
    asm("cvt.rna.tf32.f32 %0, %1;" : "=r"(u) : "f"(f));
    return u;
}
__device__ __forceinline__ void cp16(uint32_t smem_dst, const void* gptr) {
    asm volatile("cp.async.cg.shared.global [%0], [%1], 16;\n"
                 :: "r"(smem_dst), "l"(gptr));
}
__device__ __forceinline__ void cp_commit() {
    asm volatile("cp.async.commit_group;\n" ::: "memory");
}
template <int N>
__device__ __forceinline__ void cp_wait() {
    asm volatile("cp.async.wait_group %0;\n" :: "n"(N) : "memory");
}
__device__ __forceinline__ void mma_tf32(float* c, const uint32_t* a, const uint32_t* b) {
    asm volatile(
        "mma.sync.aligned.m16n8k8.row.col.f32.tf32.tf32.f32 "
        "{%0,%1,%2,%3},{%4,%5,%6,%7},{%8,%9},{%0,%1,%2,%3};"
        : "+f"(c[0]), "+f"(c[1]), "+f"(c[2]), "+f"(c[3])
        : "r"(a[0]), "r"(a[1]), "r"(a[2]), "r"(a[3]), "r"(b[0]), "r"(b[1]));
}

// ---------------------------------------------------------------------------
// Fused double LayerNorm
// ---------------------------------------------------------------------------
__global__ __launch_bounds__(256) void ln2_kernel(
    const float* __restrict__ x,
    const float* __restrict__ ga, const float* __restrict__ ba,
    const float* __restrict__ gb, const float* __restrict__ bb,
    float* __restrict__ out)
{
    __shared__ float red[16];
    __shared__ float bc[2];
    const int row = blockIdx.x, tid = threadIdx.x;
    const float4 v = *(const float4*)(x + (size_t)row * CD + tid * 4);

    float s  = v.x + v.y + v.z + v.w;
    float s2 = v.x*v.x + v.y*v.y + v.z*v.z + v.w*v.w;
    #pragma unroll
    for (int o = 16; o; o >>= 1) {
        s  += __shfl_xor_sync(~0u, s,  o);
        s2 += __shfl_xor_sync(~0u, s2, o);
    }
    if ((tid & 31) == 0) { red[(tid >> 5)*2] = s; red[(tid >> 5)*2 + 1] = s2; }
    __syncthreads();
    if (tid == 0) {
        float a = 0.f, b2 = 0.f;
        #pragma unroll
        for (int w = 0; w < 8; w++) { a += red[w*2]; b2 += red[w*2 + 1]; }
        float mu  = a * (1.f / CD);
        float var = b2 * (1.f / CD) - mu * mu;
        bc[0] = mu; bc[1] = rsqrtf(var + 1e-5f);
    }
    __syncthreads();
    float mu = bc[0], rstd = bc[1];
    __syncthreads();

    const float4 g4 = *(const float4*)(ga + tid * 4);
    const float4 b4 = *(const float4*)(ba + tid * 4);
    float y[4];
    y[0] = (v.x - mu) * rstd * g4.x + b4.x;
    y[1] = (v.y - mu) * rstd * g4.y + b4.y;
    y[2] = (v.z - mu) * rstd * g4.z + b4.z;
    y[3] = (v.w - mu) * rstd * g4.w + b4.w;

    s  = y[0] + y[1] + y[2] + y[3];
    s2 = y[0]*y[0] + y[1]*y[1] + y[2]*y[2] + y[3]*y[3];
    #pragma unroll
    for (int o = 16; o; o >>= 1) {
        s  += __shfl_xor_sync(~0u, s,  o);
        s2 += __shfl_xor_sync(~0u, s2, o);
    }
    if ((tid & 31) == 0) { red[(tid >> 5)*2] = s; red[(tid >> 5)*2 + 1] = s2; }
    __syncthreads();
    if (tid == 0) {
        float a = 0.f, b2 = 0.f;
        #pragma unroll
        for (int w = 0; w < 8; w++) { a += red[w*2]; b2 += red[w*2 + 1]; }
        float mu2  = a * (1.f / CD);
        float var2 = b2 * (1.f / CD) - mu2 * mu2;
        bc[0] = mu2; bc[1] = rsqrtf(var2 + 1e-5f);
    }
    __syncthreads();
    mu = bc[0]; rstd = bc[1];

    const float4 g24 = *(const float4*)(gb + tid * 4);
    const float4 b24 = *(const float4*)(bb + tid * 4);
    float4 o;
    o.x = (y[0] - mu) * rstd * g24.x + b24.x;
    o.y = (y[1] - mu) * rstd * g24.y + b24.y;
    o.z = (y[2] - mu) * rstd * g24.z + b24.z;
    o.w = (y[3] - mu) * rstd * g24.w + b24.w;
    *(float4*)(out + (size_t)row * CD + tid * 4) = o;
}

__global__ __launch_bounds__(256) void ln1_kernel(
    const float* __restrict__ x,
    const float* __restrict__ g, const float* __restrict__ b,
    float* __restrict__ out)
{
    __shared__ float red[16];
    __shared__ float bc[2];
    const int row = blockIdx.x, tid = threadIdx.x;
    const float4 v = *(const float4*)(x + (size_t)row * CD + tid * 4);

    float s  = v.x + v.y + v.z + v.w;
    float s2 = v.x*v.x + v.y*v.y + v.z*v.z + v.w*v.w;
    #pragma unroll
    for (int o = 16; o; o >>= 1) {
        s  += __shfl_xor_sync(~0u, s,  o);
        s2 += __shfl_xor_sync(~0u, s2, o);
    }
    if ((tid & 31) == 0) { red[(tid >> 5)*2] = s; red[(tid >> 5)*2 + 1] = s2; }
    __syncthreads();
    if (tid == 0) {
        float a = 0.f, b2 = 0.f;
        #pragma unroll
        for (int w = 0; w < 8; w++) { a += red[w*2]; b2 += red[w*2 + 1]; }
        float mu  = a * (1.f / CD);
        float var = b2 * (1.f / CD) - mu * mu;
        bc[0] = mu; bc[1] = rsqrtf(var + 1e-5f);
    }
    __syncthreads();
    const float mu = bc[0], rstd = bc[1];
    const float4 g4 = *(const float4*)(g + tid * 4);
    const float4 b4 = *(const float4*)(b + tid * 4);
    float4 o;
    o.x = (v.x - mu) * rstd * g4.x + b4.x;
    o.y = (v.y - mu) * rstd * g4.y + b4.y;
    o.z = (v.z - mu) * rstd * g4.z + b4.z;
    o.w = (v.w - mu) * rstd * g4.w + b4.w;
    *(float4*)(out + (size_t)row * CD + tid * 4) = o;
}

// ---------------------------------------------------------------------------
// TF32 tensor-core GEMM v4: 128x128 tile, BK=16, 8 warps (2x4), warp 64x32.
// 4-stage cp.async ring, ONE syncthreads per k-tile, pointer-bump addressing,
// smem carveout forced to max so 2 CTAs/SM co-reside (64KB each).
//   A smem: [m][k'] k' = k ^ (4*((m>>1)&3)), row stride 16
//   B smem: [k][n'] n' = n ^ (8*k),          row stride 128
// ---------------------------------------------------------------------------
#define GSTG 4
#define STG_BYTES 8192                       // 2048 floats per array per stage
#define GEMM_SMEM (GSTG * STG_BYTES * 2)     // 65536

__global__ __launch_bounds__(256, 2) void gemm_tc(
    const float* __restrict__ A, const float* __restrict__ W,
    const float* __restrict__ bias, const float* __restrict__ res,
    float* __restrict__ Cc, int M, int N, int K, int act)
{
    extern __shared__ float gsm[];
    float* Asm = gsm;                        // [4][2048]
    float* Bsm = gsm + GSTG * 2048;          // [4][2048]

    const int tid  = threadIdx.x;
    const int lane = tid & 31;
    const int warp = tid >> 5;
    const int wm = warp & 1;
    const int wn = warp >> 1;
    const int bm = blockIdx.y * 128;
    const int bn = blockIdx.x * 128;

    // Per-thread fixed smem byte offsets (within a stage)
    const int am  = (tid + 0)   >> 2,  ak  = (tid + 0)   & 3;
    const int am2 = (tid + 256) >> 2,  ak2 = (tid + 256) & 3;
    const int bk  = (tid + 0)   >> 5,  bn4 = (tid + 0)   & 31;
    const int bk2 = (tid + 256) >> 5,  bn42= (tid + 256) & 31;

    const uint32_t sA = (uint32_t)__cvta_generic_to_shared(Asm);
    const uint32_t sB = (uint32_t)__cvta_generic_to_shared(Bsm);
    const uint32_t aD1 = sA + (uint32_t)(am * 16 + ((ak * 4) ^ (4 * ((am >> 1) & 3)))) * 4u;
    const uint32_t aD2 = sA + (uint32_t)(am2 * 16 + ((ak2 * 4) ^ (4 * ((am2 >> 1) & 3)))) * 4u;
    const uint32_t bD1 = sB + (uint32_t)(bk * 128 + ((bn4 * 4) ^ (8 * bk))) * 4u;
    const uint32_t bD2 = sB + (uint32_t)(bk2 * 128 + ((bn42 * 4) ^ (8 * bk2))) * 4u;

    // Gmem pointers, bumped each issue
    const float* gA1 = A + (size_t)(bm + am)  * K + ak * 4;
    const float* gA2 = A + (size_t)(bm + am2) * K + ak2 * 4;
    const float* gB1 = W + (size_t)bk  * N + bn + bn4 * 4;
    const float* gB2 = W + (size_t)bk2 * N + bn + bn42 * 4;
    const size_t bStep = (size_t)16 * N;

    float acc[4][4][4];
    #pragma unroll
    for (int i = 0; i < 4; i++)
        #pragma unroll
        for (int j = 0; j < 4; j++)
            #pragma unroll
            for (int r = 0; r < 4; r++) acc[i][j][r] = 0.f;

    auto issue = [&](int s) {
        const uint32_t so = (uint32_t)s << 13;   // s * 8192 bytes
        cp16(aD1 + so, gA1);
        cp16(aD2 + so, gA2);
        cp16(bD1 + so, gB1);
        cp16(bD2 + so, gB2);
        gA1 += 16; gA2 += 16; gB1 += bStep; gB2 += bStep;
    };

    issue(0); cp_commit();
    issue(1); cp_commit();
    issue(2); cp_commit();

    const int nK = K >> 4;
    const int r4 = lane >> 2;
    const int c4 = lane & 3;

    for (int kt = 0; kt < nK; kt++) {
        cp_wait<2>();
        __syncthreads();
        // refill slot (kt+3)&3 == (kt-1)&3, freed by the barrier above
        if (kt + 3 < nK) issue((kt + 3) & 3);
        cp_commit();

        const int cur = kt & 3;
        const float* Ap = Asm + cur * 2048;
        const float* Bp = Bsm + cur * 2048;

        #pragma unroll
        for (int k8 = 0; k8 < 2; k8++) {
            const int kb = k8 * 8 + c4;
            uint32_t af[4][4], bf[4][2];
            #pragma unroll
            for (int mf = 0; mf < 4; mf++) {
                const int m0 = wm * 64 + mf * 16 + r4;
                const int xm = 4 * ((m0 >> 1) & 3);
                const float* p = Ap + m0 * 16;
                af[mf][0] = f2tf32(p[kb ^ xm]);
                af[mf][1] = f2tf32(p[128 + (kb ^ xm)]);
                af[mf][2] = f2tf32(p[(kb + 4) ^ xm]);
                af[mf][3] = f2tf32(p[128 + ((kb + 4) ^ xm)]);
            }
            #pragma unroll
            for (int nf = 0; nf < 4; nf++) {
                const int n = wn * 32 + nf * 8 + r4;
                bf[nf][0] = __float_as_uint(Bp[kb * 128 + (n ^ (8 * kb))]);
                bf[nf][1] = __float_as_uint(Bp[(kb + 4) * 128 + (n ^ (8 * (kb + 4)))]);
            }
            #pragma unroll
            for (int mf = 0; mf < 4; mf++)
                #pragma unroll
                for (int nf = 0; nf < 4; nf++)
                    mma_tf32(acc[mf][nf], af[mf], bf[nf]);
        }
    }

    // epilogue
    #pragma unroll
    for (int mf = 0; mf < 4; mf++) {
        #pragma unroll
        for (int nf = 0; nf < 4; nf++) {
            const int col = bn + wn * 32 + nf * 8 + c4 * 2;
            const float bx = bias[col], by = bias[col + 1];
            #pragma unroll
            for (int h = 0; h < 2; h++) {
                const int row = bm + wm * 64 + mf * 16 + r4 + h * 8;
                float ox = acc[mf][nf][h * 2 + 0] + bx;
                float oy = acc[mf][nf][h * 2 + 1] + by;
                if (act) {
                    ox *= 1.f / (1.f + __expf(-ox));
                    oy *= 1.f / (1.f + __expf(-oy));
                }
                const size_t off = (size_t)row * N + col;
                if (res) {
                    const float2 rr = *(const float2*)(res + off);
                    ox += rr.x; oy += rr.y;
                }
                float2 o; o.x = ox; o.y = oy;
                *(float2*)(Cc + off) = o;
            }
        }
    }
}

// ---------------------------------------------------------------------------
// Flash attention on tensor cores (R3 kernel, carveout raised host-side)
// ---------------------------------------------------------------------------
#define PQ 68
#define PV 72
#define ATTN_SMEM ((64*PQ + 2*64*PQ + 2*64*PV + 4*16*PQ) * 4)

__global__ __launch_bounds__(128) void attn_tc(
    const float* __restrict__ Q, const float* __restrict__ Kg,
    const float* __restrict__ Vg, float* __restrict__ O)
{
    extern __shared__ float sm[];
    float* Qs = sm;
    float* Ks = Qs + 64 * PQ;
    float* Vs = Ks + 2 * 64 * PQ;
    float* Ps = Vs + 2 * 64 * PV;

    const int bh = blockIdx.y;
    const int b = bh >> 4, h = bh & 15;
    const int qt = blockIdx.x;
    const int q0 = qt * 64;
    const int tid = threadIdx.x;
    const int lane = tid & 31;
    const int warp = tid >> 5;
    const int r4 = lane >> 2;
    const int c4 = lane & 3;
    const size_t base = (size_t)b * TD * CD + (size_t)h * HD;

    const uint32_t sQ = (uint32_t)__cvta_generic_to_shared(Qs);
    const uint32_t sK = (uint32_t)__cvta_generic_to_shared(Ks);
    const uint32_t sV = (uint32_t)__cvta_generic_to_shared(Vs);

    #pragma unroll
    for (int i = 0; i < 8; i++) {
        const int idx = tid + i * 128;
        const int row = idx >> 4, cc = idx & 15;
        cp16(sQ + (uint32_t)(row * PQ + cc * 4) * 4u,
             Q + base + (size_t)(q0 + row) * CD + cc * 4);
    }
    auto issue_kv = [&](int buf, int k0) {
        #pragma unroll
        for (int i = 0; i < 8; i++) {
            const int idx = tid + i * 128;
            const int row = idx >> 4, cc = idx & 15;
            const size_t g = base + (size_t)(k0 + row) * CD + cc * 4;
            cp16(sK + (uint32_t)(buf * 64 * PQ + row * PQ + cc * 4) * 4u, Kg + g);
            cp16(sV + (uint32_t)(buf * 64 * PV + row * PV + cc * 4) * 4u, Vg + g);
        }
    };
    issue_kv(0, 0);
    cp_commit();
    if (qt >= 1) { issue_kv(1, 64); cp_commit(); }

    uint32_t qf[8][4];
    float oacc[8][4];
    #pragma unroll
    for (int nt = 0; nt < 8; nt++)
        #pragma unroll
        for (int r = 0; r < 4; r++) oacc[nt][r] = 0.f;
    float m0 = -1e30f, m1 = -1e30f, l0 = 0.f, l1 = 0.f;

    float* Pw = Ps + warp * 16 * PQ;

    for (int kt = 0; kt <= qt; kt++) {
        if (kt + 1 <= qt) cp_wait<1>(); else cp_wait<0>();
        __syncthreads();
        const int cur = kt & 1;
        const float* Kp = Ks + cur * 64 * PQ;
        const float* Vp = Vs + cur * 64 * PV;

        if (kt == 0) {
            const float* qp = Qs + (warp * 16 + r4) * PQ;
            #pragma unroll
            for (int ks = 0; ks < 8; ks++) {
                const int c = ks * 8 + c4;
                qf[ks][0] = __float_as_uint(qp[c] * 0.125f);
                qf[ks][1] = __float_as_uint(qp[8 * PQ + c] * 0.125f);
                qf[ks][2] = __float_as_uint(qp[c + 4] * 0.125f);
                qf[ks][3] = __float_as_uint(qp[8 * PQ + c + 4] * 0.125f);
            }
        }

        float sacc[8][4];
        #pragma unroll
        for (int nt = 0; nt < 8; nt++)
            #pragma unroll
            for (int r = 0; r < 4; r++) sacc[nt][r] = 0.f;

        #pragma unroll
        for (int ks = 0; ks < 8; ks++) {
            const int k = ks * 8 + c4;
            #pragma unroll
            for (int nt = 0; nt < 8; nt++) {
                const int n = nt * 8 + r4;
                uint32_t bf[2];
                bf[0] = __float_as_uint(Kp[n * PQ + k]);
                bf[1] = __float_as_uint(Kp[n * PQ + k + 4]);
                mma_tf32(sacc[nt], qf[ks], bf);
            }
        }

        if (kt == qt) {
            const int row0 = warp * 16 + r4;
            #pragma unroll
            for (int nt = 0; nt < 8; nt++) {
                const int cb = nt * 8 + 2 * c4;
                if (cb + 0 > row0)     sacc[nt][0] = -1e30f;
                if (cb + 1 > row0)     sacc[nt][1] = -1e30f;
                if (cb + 0 > row0 + 8) sacc[nt][2] = -1e30f;
                if (cb + 1 > row0 + 8) sacc[nt][3] = -1e30f;
            }
        }

        float rm0 = -1e30f, rm1 = -1e30f;
        #pragma unroll
        for (int nt = 0; nt < 8; nt++) {
            rm0 = fmaxf(rm0, fmaxf(sacc[nt][0], sacc[nt][1]));
            rm1 = fmaxf(rm1, fmaxf(sacc[nt][2], sacc[nt][3]));
        }
        rm0 = fmaxf(rm0, __shfl_xor_sync(~0u, rm0, 1));
        rm0 = fmaxf(rm0, __shfl_xor_sync(~0u, rm0, 2));
        rm1 = fmaxf(rm1, __shfl_xor_sync(~0u, rm1, 1));
        rm1 = fmaxf(rm1, __shfl_xor_sync(~0u, rm1, 2));

        const float mn0 = fmaxf(m0, rm0), mn1 = fmaxf(m1, rm1);
        const float f0 = __expf(m0 - mn0), f1 = __expf(m1 - mn1);
        m0 = mn0; m1 = mn1;

        float rs0 = 0.f, rs1 = 0.f;
        #pragma unroll
        for (int nt = 0; nt < 8; nt++) {
            float p0 = __expf(sacc[nt][0] - mn0);
            float p1 = __expf(sacc[nt][1] - mn0);
            float p2 = __expf(sacc[nt][2] - mn1);
            float p3 = __expf(sacc[nt][3] - mn1);
            rs0 += p0 + p1; rs1 += p2 + p3;
            float2 w0; w0.x = p0; w0.y = p1;
            float2 w1; w1.x = p2; w1.y = p3;
            *(float2*)(Pw + r4 * PQ + nt * 8 + 2 * c4)       = w0;
            *(float2*)(Pw + (r4 + 8) * PQ + nt * 8 + 2 * c4) = w1;
        }
        rs0 += __shfl_xor_sync(~0u, rs0, 1);
        rs0 += __shfl_xor_sync(~0u, rs0, 2);
        rs1 += __shfl_xor_sync(~0u, rs1, 1);
        rs1 += __shfl_xor_sync(~0u, rs1, 2);
        l0 = l0 * f0 + rs0;
        l1 = l1 * f1 + rs1;

        #pragma unroll
        for (int nt = 0; nt < 8; nt++) {
            oacc[nt][0] *= f0; oacc[nt][1] *= f0;
            oacc[nt][2] *= f1; oacc[nt][3] *= f1;
        }
        __syncwarp();

        #pragma unroll
        for (int ks = 0; ks < 8; ks++) {
            const int c = ks * 8 + c4;
            uint32_t af[4];
            af[0] = __float_as_uint(Pw[r4 * PQ + c]);
            af[1] = __float_as_uint(Pw[(r4 + 8) * PQ + c]);
            af[2] = __float_as_uint(Pw[r4 * PQ + c + 4]);
            af[3] = __float_as_uint(Pw[(r4 + 8) * PQ + c + 4]);
            #pragma unroll
            for (int nt = 0; nt < 8; nt++) {
                const int n = nt * 8 + r4;
                uint32_t bf[2];
                bf[0] = __float_as_uint(Vp[c * PV + n]);
                bf[1] = __float_as_uint(Vp[(c + 4) * PV + n]);
                mma_tf32(oacc[nt], af, bf);
            }
        }

        __syncthreads();
        if (kt + 2 <= qt) { issue_kv(cur, (kt + 2) * 64); cp_commit(); }
    }

    const float inv0 = 1.f / l0, inv1 = 1.f / l1;
    const int row0 = q0 + warp * 16 + r4;
    #pragma unroll
    for (int nt = 0; nt < 8; nt++) {
        const int col = h * HD + nt * 8 + 2 * c4;
        float2 o0, o1;
        o0.x = oacc[nt][0] * inv0; o0.y = oacc[nt][1] * inv0;
        o1.x = oacc[nt][2] * inv1; o1.y = oacc[nt][3] * inv1;
        *(float2*)(O + (size_t)(b * TD + row0) * CD + col)     = o0;
        *(float2*)(O + (size_t)(b * TD + row0 + 8) * CD + col) = o1;
    }
}

// ---------------------------------------------------------------------------
// Launch
// ---------------------------------------------------------------------------
extern "C" void kernel_launch(void* const* d_in, const int* in_sizes, int n_in,
                              void* d_out, int out_size)
{
    const float* x      = (const float*)d_in[0];
    const float* ln_a_g = (const float*)d_in[1];
    const float* ln_a_b = (const float*)d_in[2];
    const float* ln_b_g = (const float*)d_in[3];
    const float* ln_b_b = (const float*)d_in[4];
    const float* ln_c_g = (const float*)d_in[5];
    const float* ln_c_b = (const float*)d_in[6];
    const float* Wq = (const float*)d_in[7];  const float* bq = (const float*)d_in[8];
    const float* Wk = (const float*)d_in[9];  const float* bk = (const float*)d_in[10];
    const float* Wv = (const float*)d_in[11]; const float* bv = (const float*)d_in[12];
    const float* Wo = (const float*)d_in[13]; const float* bo = (const float*)d_in[14];
    const float* We = (const float*)d_in[15]; const float* be = (const float*)d_in[16];
    const float* Wd = (const float*)d_in[17]; const float* bd = (const float*)d_in[18];
    float* out = (float*)d_out;

    float *t, *q, *k, *v, *ctx, *x2, *h;
    cudaGetSymbolAddress((void**)&t,   g_t);
    cudaGetSymbolAddress((void**)&q,   g_q);
    cudaGetSymbolAddress((void**)&k,   g_k);
    cudaGetSymbolAddress((void**)&v,   g_v);
    cudaGetSymbolAddress((void**)&ctx, g_ctx);
    cudaGetSymbolAddress((void**)&x2,  g_x2);
    cudaGetSymbolAddress((void**)&h,   g_h);

    cudaFuncSetAttribute(gemm_tc, cudaFuncAttributeMaxDynamicSharedMemorySize,
                         GEMM_SMEM);
    cudaFuncSetAttribute(gemm_tc, cudaFuncAttributePreferredSharedMemoryCarveout,
                         100);
    cudaFuncSetAttribute(attn_tc, cudaFuncAttributeMaxDynamicSharedMemorySize,
                         ATTN_SMEM);
    cudaFuncSetAttribute(attn_tc, cudaFuncAttributePreferredSharedMemoryCarveout,
                         100);

    // 1. t = LN_b(LN_a(x))
    ln2_kernel<<<NT, 256>>>(x, ln_a_g, ln_a_b, ln_b_g, ln_b_b, t);

    // 2. QKV projections
    {
        dim3 grid(CD / 128, NT / 128);
        gemm_tc<<<grid, 256, GEMM_SMEM>>>(t, Wq, bq, nullptr, q, NT, CD, CD, 0);
        gemm_tc<<<grid, 256, GEMM_SMEM>>>(t, Wk, bk, nullptr, k, NT, CD, CD, 0);
        gemm_tc<<<grid, 256, GEMM_SMEM>>>(t, Wv, bv, nullptr, v, NT, CD, CD, 0);
    }

    // 3. causal attention
    {
        dim3 grid(TD / 64, BD * HN);
        attn_tc<<<grid, 128, ATTN_SMEM>>>(q, k, v, ctx);
    }

    // 4. x2 = x + ctx @ Wo + bo
    {
        dim3 grid(CD / 128, NT / 128);
        gemm_tc<<<grid, 256, GEMM_SMEM>>>(ctx, Wo, bo, x, x2, NT, CD, CD, 0);
    }

    // 5. t = LN_c(x2)
    ln1_kernel<<<NT, 256>>>(x2, ln_c_g, ln_c_b, t);

    // 6. h = silu(t @ We + be)
    {
        dim3 grid(DFFD / 128, NT / 128);
        gemm_tc<<<grid, 256, GEMM_SMEM>>>(t, We, be, nullptr, h, NT, DFFD, CD, 1);
    }

    // 7. out = x2 + h @ Wd + bd
    {
        dim3 grid(CD / 128, NT / 128);
        gemm_tc<<<grid, 256, GEMM_SMEM>>>(h, Wd, bd, x2, out, NT, CD, DFFD, 0);
    }
}

// round 7
// speedup vs baseline: 1.2417x; 1.0869x over previous
#include <cuda_runtime.h>
#include <math.h>
#include <stdint.h>

// Problem dims
#define BD   2
#define TD   2048
#define CD   1024
#define HN   16
#define HD   64
#define DFFD 4096
#define NT   (BD * TD)   // 4096 tokens

// ---------------------------------------------------------------------------
// Scratch
// ---------------------------------------------------------------------------
__device__ float g_t  [(size_t)NT * CD];
__device__ float g_q  [(size_t)NT * CD];
__device__ float g_k  [(size_t)NT * CD];
__device__ float g_v  [(size_t)NT * CD];
__device__ float g_ctx[(size_t)NT * CD];
__device__ float g_x2 [(size_t)NT * CD];
__device__ float g_h  [(size_t)NT * DFFD];

// ---------------------------------------------------------------------------
// Helpers
// ---------------------------------------------------------------------------
__device__ __forceinline__ uint32_t f2tf32(float f) {
    uint32_t u;
    asm("cvt.rna.tf32.f32 %0, %1;" : "=r"(u) : "f"(f));
    return u;
}
__device__ __forceinline__ void cp16(uint32_t smem_dst, const void* gptr) {
    asm volatile("cp.async.cg.shared.global [%0], [%1], 16;\n"
                 :: "r"(smem_dst), "l"(gptr));
}
__device__ __forceinline__ void cp_commit() {
    asm volatile("cp.async.commit_group;\n" ::: "memory");
}
template <int N>
__device__ __forceinline__ void cp_wait() {
    asm volatile("cp.async.wait_group %0;\n" :: "n"(N) : "memory");
}
__device__ __forceinline__ void mma_tf32(float* c, const uint32_t* a, const uint32_t* b) {
    asm volatile(
        "mma.sync.aligned.m16n8k8.row.col.f32.tf32.tf32.f32 "
        "{%0,%1,%2,%3},{%4,%5,%6,%7},{%8,%9},{%0,%1,%2,%3};"
        : "+f"(c[0]), "+f"(c[1]), "+f"(c[2]), "+f"(c[3])
        : "r"(a[0]), "r"(a[1]), "r"(a[2]), "r"(a[3]), "r"(b[0]), "r"(b[1]));
}

// ---------------------------------------------------------------------------
// Fused double LayerNorm
// ---------------------------------------------------------------------------
__global__ __launch_bounds__(256) void ln2_kernel(
    const float* __restrict__ x,
    const float* __restrict__ ga, const float* __restrict__ ba,
    const float* __restrict__ gb, const float* __restrict__ bb,
    float* __restrict__ out)
{
    __shared__ float red[16];
    __shared__ float bc[2];
    const int row = blockIdx.x, tid = threadIdx.x;
    const float4 v = *(const float4*)(x + (size_t)row * CD + tid * 4);

    float s  = v.x + v.y + v.z + v.w;
    float s2 = v.x*v.x + v.y*v.y + v.z*v.z + v.w*v.w;
    #pragma unroll
    for (int o = 16; o; o >>= 1) {
        s  += __shfl_xor_sync(~0u, s,  o);
        s2 += __shfl_xor_sync(~0u, s2, o);
    }
    if ((tid & 31) == 0) { red[(tid >> 5)*2] = s; red[(tid >> 5)*2 + 1] = s2; }
    __syncthreads();
    if (tid == 0) {
        float a = 0.f, b2 = 0.f;
        #pragma unroll
        for (int w = 0; w < 8; w++) { a += red[w*2]; b2 += red[w*2 + 1]; }
        float mu  = a * (1.f / CD);
        float var = b2 * (1.f / CD) - mu * mu;
        bc[0] = mu; bc[1] = rsqrtf(var + 1e-5f);
    }
    __syncthreads();
    float mu = bc[0], rstd = bc[1];
    __syncthreads();

    const float4 g4 = *(const float4*)(ga + tid * 4);
    const float4 b4 = *(const float4*)(ba + tid * 4);
    float y[4];
    y[0] = (v.x - mu) * rstd * g4.x + b4.x;
    y[1] = (v.y - mu) * rstd * g4.y + b4.y;
    y[2] = (v.z - mu) * rstd * g4.z + b4.z;
    y[3] = (v.w - mu) * rstd * g4.w + b4.w;

    s  = y[0] + y[1] + y[2] + y[3];
    s2 = y[0]*y[0] + y[1]*y[1] + y[2]*y[2] + y[3]*y[3];
    #pragma unroll
    for (int o = 16; o; o >>= 1) {
        s  += __shfl_xor_sync(~0u, s,  o);
        s2 += __shfl_xor_sync(~0u, s2, o);
    }
    if ((tid & 31) == 0) { red[(tid >> 5)*2] = s; red[(tid >> 5)*2 + 1] = s2; }
    __syncthreads();
    if (tid == 0) {
        float a = 0.f, b2 = 0.f;
        #pragma unroll
        for (int w = 0; w < 8; w++) { a += red[w*2]; b2 += red[w*2 + 1]; }
        float mu2  = a * (1.f / CD);
        float var2 = b2 * (1.f / CD) - mu2 * mu2;
        bc[0] = mu2; bc[1] = rsqrtf(var2 + 1e-5f);
    }
    __syncthreads();
    mu = bc[0]; rstd = bc[1];

    const float4 g24 = *(const float4*)(gb + tid * 4);
    const float4 b24 = *(const float4*)(bb + tid * 4);
    float4 o;
    o.x = (y[0] - mu) * rstd * g24.x + b24.x;
    o.y = (y[1] - mu) * rstd * g24.y + b24.y;
    o.z = (y[2] - mu) * rstd * g24.z + b24.z;
    o.w = (y[3] - mu) * rstd * g24.w + b24.w;
    *(float4*)(out + (size_t)row * CD + tid * 4) = o;
}

__global__ __launch_bounds__(256) void ln1_kernel(
    const float* __restrict__ x,
    const float* __restrict__ g, const float* __restrict__ b,
    float* __restrict__ out)
{
    __shared__ float red[16];
    __shared__ float bc[2];
    const int row = blockIdx.x, tid = threadIdx.x;
    const float4 v = *(const float4*)(x + (size_t)row * CD + tid * 4);

    float s  = v.x + v.y + v.z + v.w;
    float s2 = v.x*v.x + v.y*v.y + v.z*v.z + v.w*v.w;
    #pragma unroll
    for (int o = 16; o; o >>= 1) {
        s  += __shfl_xor_sync(~0u, s,  o);
        s2 += __shfl_xor_sync(~0u, s2, o);
    }
    if ((tid & 31) == 0) { red[(tid >> 5)*2] = s; red[(tid >> 5)*2 + 1] = s2; }
    __syncthreads();
    if (tid == 0) {
        float a = 0.f, b2 = 0.f;
        #pragma unroll
        for (int w = 0; w < 8; w++) { a += red[w*2]; b2 += red[w*2 + 1]; }
        float mu  = a * (1.f / CD);
        float var = b2 * (1.f / CD) - mu * mu;
        bc[0] = mu; bc[1] = rsqrtf(var + 1e-5f);
    }
    __syncthreads();
    const float mu = bc[0], rstd = bc[1];
    const float4 g4 = *(const float4*)(g + tid * 4);
    const float4 b4 = *(const float4*)(b + tid * 4);
    float4 o;
    o.x = (v.x - mu) * rstd * g4.x + b4.x;
    o.y = (v.y - mu) * rstd * g4.y + b4.y;
    o.z = (v.z - mu) * rstd * g4.z + b4.z;
    o.w = (v.w - mu) * rstd * g4.w + b4.w;
    *(float4*)(out + (size_t)row * CD + tid * 4) = o;
}

// ---------------------------------------------------------------------------
// TF32 tensor-core GEMM v5: 128x128 tile, BK=8, 4-stage STATIC smem ring,
// one syncthreads per 8-k tile, unrolled x4 so stage offsets are immediates.
// 8 warps (2x4), warp tile 64x32. cvt.rna on A, raw-bit B.
//   A smem: [m][slot] slot = k ^ (4*((m>>2)&1)), row stride 8
//   B smem: [k][n']   n'   = n ^ (8*k),          row stride 128
// grid.z selects {W0,W1,W2} for fused QKV (pass same ptr x3 for single gemm).
// ---------------------------------------------------------------------------
__global__ __launch_bounds__(256, 2) void gemm_tc(
    const float* __restrict__ A,
    const float* __restrict__ W0, const float* __restrict__ W1, const float* __restrict__ W2,
    const float* __restrict__ b0, const float* __restrict__ b1, const float* __restrict__ b2,
    const float* __restrict__ res,
    float* __restrict__ C0, float* __restrict__ C1, float* __restrict__ C2,
    int M, int N, int K, int act)
{
    __shared__ float As[4][128 * 8];   // 16 KB
    __shared__ float Bs[4][8 * 128];   // 16 KB

    const int z = blockIdx.z;
    const float* W    = (z == 0) ? W0 : (z == 1) ? W1 : W2;
    const float* bias = (z == 0) ? b0 : (z == 1) ? b1 : b2;
    float*       Cc   = (z == 0) ? C0 : (z == 1) ? C1 : C2;

    const int tid  = threadIdx.x;
    const int lane = tid & 31;
    const int warp = tid >> 5;
    const int wm = warp & 1;
    const int wn = warp >> 1;
    const int bm = blockIdx.y * 128;
    const int bn = blockIdx.x * 128;

    // cp.async: A 256 chunks (1/thread), B 256 chunks (1/thread)
    const int am = tid >> 1, aj = tid & 1;
    const int bk = tid >> 5, bc = tid & 31;

    const uint32_t aD = (uint32_t)__cvta_generic_to_shared(&As[0][0])
                      + (uint32_t)(am * 8 + 4 * (aj ^ ((am >> 2) & 1))) * 4u;
    const uint32_t bD = (uint32_t)__cvta_generic_to_shared(&Bs[0][0])
                      + (uint32_t)(bk * 128 + ((bc * 4) ^ (8 * bk))) * 4u;

    const float* gA = A + (size_t)(bm + am) * K + aj * 4;
    const float* gB = W + (size_t)bk * N + bn + bc * 4;
    const size_t bStep = (size_t)8 * N;

    float acc[4][4][4];
    #pragma unroll
    for (int i = 0; i < 4; i++)
        #pragma unroll
        for (int j = 0; j < 4; j++)
            #pragma unroll
            for (int r = 0; r < 4; r++) acc[i][j][r] = 0.f;

    // prologue: fill stages 0..2
    cp16(aD + 0u * 4096u, gA); cp16(bD + 0u * 4096u, gB);
    gA += 8; gB += bStep; cp_commit();
    cp16(aD + 1u * 4096u, gA); cp16(bD + 1u * 4096u, gB);
    gA += 8; gB += bStep; cp_commit();
    cp16(aD + 2u * 4096u, gA); cp16(bD + 2u * 4096u, gB);
    gA += 8; gB += bStep; cp_commit();

    const int nK = K >> 3;               // multiple of 4 for our shapes
    const int r4 = lane >> 2;
    const int c4 = lane & 3;
    const int xb = 4 * ((r4 >> 2) & 1);  // A swizzle bit for this thread
    const int oA = c4 ^ xb;

    for (int kt = 0; kt < nK; kt += 4) {
        #pragma unroll
        for (int s = 0; s < 4; s++) {
            cp_wait<2>();
            __syncthreads();
            // refill slot (s+3)&3 (freed last iteration) with tile kt+s+3
            if (kt + s + 3 < nK) {
                const uint32_t so = (uint32_t)(((s + 3) & 3) * 4096);
                cp16(aD + so, gA);
                cp16(bD + so, gB);
                gA += 8; gB += bStep;
            }
            cp_commit();

            const float* Ap = &As[s][0];
            const float* Bp = &Bs[s][0];

            uint32_t af[4][4], bf[4][2];
            #pragma unroll
            for (int mf = 0; mf < 4; mf++) {
                const float* p = Ap + (wm * 64 + mf * 16 + r4) * 8;
                af[mf][0] = f2tf32(p[oA]);
                af[mf][1] = f2tf32(p[64 + oA]);
                af[mf][2] = f2tf32(p[oA ^ 4]);
                af[mf][3] = f2tf32(p[64 + (oA ^ 4)]);
            }
            #pragma unroll
            for (int nf = 0; nf < 4; nf++) {
                const int n = wn * 32 + nf * 8 + r4;
                bf[nf][0] = __float_as_uint(Bp[c4 * 128 + (n ^ (8 * c4))]);
                bf[nf][1] = __float_as_uint(Bp[(c4 + 4) * 128 + (n ^ (8 * (c4 + 4)))]);
            }
            #pragma unroll
            for (int mf = 0; mf < 4; mf++)
                #pragma unroll
                for (int nf = 0; nf < 4; nf++)
                    mma_tf32(acc[mf][nf], af[mf], bf[nf]);
        }
    }

    // epilogue
    #pragma unroll
    for (int mf = 0; mf < 4; mf++) {
        #pragma unroll
        for (int nf = 0; nf < 4; nf++) {
            const int col = bn + wn * 32 + nf * 8 + c4 * 2;
            const float bx = bias[col], by = bias[col + 1];
            #pragma unroll
            for (int h = 0; h < 2; h++) {
                const int row = bm + wm * 64 + mf * 16 + r4 + h * 8;
                float ox = acc[mf][nf][h * 2 + 0] + bx;
                float oy = acc[mf][nf][h * 2 + 1] + by;
                if (act) {
                    ox *= 1.f / (1.f + __expf(-ox));
                    oy *= 1.f / (1.f + __expf(-oy));
                }
                const size_t off = (size_t)row * N + col;
                if (res) {
                    const float2 rr = *(const float2*)(res + off);
                    ox += rr.x; oy += rr.y;
                }
                float2 o; o.x = ox; o.y = oy;
                *(float2*)(Cc + off) = o;
            }
        }
    }
}

// ---------------------------------------------------------------------------
// Flash attention on tensor cores (R3 kernel)
// ---------------------------------------------------------------------------
#define PQ 68
#define PV 72
#define ATTN_SMEM ((64*PQ + 2*64*PQ + 2*64*PV + 4*16*PQ) * 4)

__global__ __launch_bounds__(128) void attn_tc(
    const float* __restrict__ Q, const float* __restrict__ Kg,
    const float* __restrict__ Vg, float* __restrict__ O)
{
    extern __shared__ float sm[];
    float* Qs = sm;
    float* Ks = Qs + 64 * PQ;
    float* Vs = Ks + 2 * 64 * PQ;
    float* Ps = Vs + 2 * 64 * PV;

    const int bh = blockIdx.y;
    const int b = bh >> 4, h = bh & 15;
    const int qt = blockIdx.x;
    const int q0 = qt * 64;
    const int tid = threadIdx.x;
    const int lane = tid & 31;
    const int warp = tid >> 5;
    const int r4 = lane >> 2;
    const int c4 = lane & 3;
    const size_t base = (size_t)b * TD * CD + (size_t)h * HD;

    const uint32_t sQ = (uint32_t)__cvta_generic_to_shared(Qs);
    const uint32_t sK = (uint32_t)__cvta_generic_to_shared(Ks);
    const uint32_t sV = (uint32_t)__cvta_generic_to_shared(Vs);

    #pragma unroll
    for (int i = 0; i < 8; i++) {
        const int idx = tid + i * 128;
        const int row = idx >> 4, cc = idx & 15;
        cp16(sQ + (uint32_t)(row * PQ + cc * 4) * 4u,
             Q + base + (size_t)(q0 + row) * CD + cc * 4);
    }
    auto issue_kv = [&](int buf, int k0) {
        #pragma unroll
        for (int i = 0; i < 8; i++) {
            const int idx = tid + i * 128;
            const int row = idx >> 4, cc = idx & 15;
            const size_t g = base + (size_t)(k0 + row) * CD + cc * 4;
            cp16(sK + (uint32_t)(buf * 64 * PQ + row * PQ + cc * 4) * 4u, Kg + g);
            cp16(sV + (uint32_t)(buf * 64 * PV + row * PV + cc * 4) * 4u, Vg + g);
        }
    };
    issue_kv(0, 0);
    cp_commit();
    if (qt >= 1) { issue_kv(1, 64); cp_commit(); }

    uint32_t qf[8][4];
    float oacc[8][4];
    #pragma unroll
    for (int nt = 0; nt < 8; nt++)
        #pragma unroll
        for (int r = 0; r < 4; r++) oacc[nt][r] = 0.f;
    float m0 = -1e30f, m1 = -1e30f, l0 = 0.f, l1 = 0.f;

    float* Pw = Ps + warp * 16 * PQ;

    for (int kt = 0; kt <= qt; kt++) {
        if (kt + 1 <= qt) cp_wait<1>(); else cp_wait<0>();
        __syncthreads();
        const int cur = kt & 1;
        const float* Kp = Ks + cur * 64 * PQ;
        const float* Vp = Vs + cur * 64 * PV;

        if (kt == 0) {
            const float* qp = Qs + (warp * 16 + r4) * PQ;
            #pragma unroll
            for (int ks = 0; ks < 8; ks++) {
                const int c = ks * 8 + c4;
                qf[ks][0] = __float_as_uint(qp[c] * 0.125f);
                qf[ks][1] = __float_as_uint(qp[8 * PQ + c] * 0.125f);
                qf[ks][2] = __float_as_uint(qp[c + 4] * 0.125f);
                qf[ks][3] = __float_as_uint(qp[8 * PQ + c + 4] * 0.125f);
            }
        }

        float sacc[8][4];
        #pragma unroll
        for (int nt = 0; nt < 8; nt++)
            #pragma unroll
            for (int r = 0; r < 4; r++) sacc[nt][r] = 0.f;

        #pragma unroll
        for (int ks = 0; ks < 8; ks++) {
            const int k = ks * 8 + c4;
            #pragma unroll
            for (int nt = 0; nt < 8; nt++) {
                const int n = nt * 8 + r4;
                uint32_t bf[2];
                bf[0] = __float_as_uint(Kp[n * PQ + k]);
                bf[1] = __float_as_uint(Kp[n * PQ + k + 4]);
                mma_tf32(sacc[nt], qf[ks], bf);
            }
        }

        if (kt == qt) {
            const int row0 = warp * 16 + r4;
            #pragma unroll
            for (int nt = 0; nt < 8; nt++) {
                const int cb = nt * 8 + 2 * c4;
                if (cb + 0 > row0)     sacc[nt][0] = -1e30f;
                if (cb + 1 > row0)     sacc[nt][1] = -1e30f;
                if (cb + 0 > row0 + 8) sacc[nt][2] = -1e30f;
                if (cb + 1 > row0 + 8) sacc[nt][3] = -1e30f;
            }
        }

        float rm0 = -1e30f, rm1 = -1e30f;
        #pragma unroll
        for (int nt = 0; nt < 8; nt++) {
            rm0 = fmaxf(rm0, fmaxf(sacc[nt][0], sacc[nt][1]));
            rm1 = fmaxf(rm1, fmaxf(sacc[nt][2], sacc[nt][3]));
        }
        rm0 = fmaxf(rm0, __shfl_xor_sync(~0u, rm0, 1));
        rm0 = fmaxf(rm0, __shfl_xor_sync(~0u, rm0, 2));
        rm1 = fmaxf(rm1, __shfl_xor_sync(~0u, rm1, 1));
        rm1 = fmaxf(rm1, __shfl_xor_sync(~0u, rm1, 2));

        const float mn0 = fmaxf(m0, rm0), mn1 = fmaxf(m1, rm1);
        const float f0 = __expf(m0 - mn0), f1 = __expf(m1 - mn1);
        m0 = mn0; m1 = mn1;

        float rs0 = 0.f, rs1 = 0.f;
        #pragma unroll
        for (int nt = 0; nt < 8; nt++) {
            float p0 = __expf(sacc[nt][0] - mn0);
            float p1 = __expf(sacc[nt][1] - mn0);
            float p2 = __expf(sacc[nt][2] - mn1);
            float p3 = __expf(sacc[nt][3] - mn1);
            rs0 += p0 + p1; rs1 += p2 + p3;
            float2 w0; w0.x = p0; w0.y = p1;
            float2 w1; w1.x = p2; w1.y = p3;
            *(float2*)(Pw + r4 * PQ + nt * 8 + 2 * c4)       = w0;
            *(float2*)(Pw + (r4 + 8) * PQ + nt * 8 + 2 * c4) = w1;
        }
        rs0 += __shfl_xor_sync(~0u, rs0, 1);
        rs0 += __shfl_xor_sync(~0u, rs0, 2);
        rs1 += __shfl_xor_sync(~0u, rs1, 1);
        rs1 += __shfl_xor_sync(~0u, rs1, 2);
        l0 = l0 * f0 + rs0;
        l1 = l1 * f1 + rs1;

        #pragma unroll
        for (int nt = 0; nt < 8; nt++) {
            oacc[nt][0] *= f0; oacc[nt][1] *= f0;
            oacc[nt][2] *= f1; oacc[nt][3] *= f1;
        }
        __syncwarp();

        #pragma unroll
        for (int ks = 0; ks < 8; ks++) {
            const int c = ks * 8 + c4;
            uint32_t af[4];
            af[0] = __float_as_uint(Pw[r4 * PQ + c]);
            af[1] = __float_as_uint(Pw[(r4 + 8) * PQ + c]);
            af[2] = __float_as_uint(Pw[r4 * PQ + c + 4]);
            af[3] = __float_as_uint(Pw[(r4 + 8) * PQ + c + 4]);
            #pragma unroll
            for (int nt = 0; nt < 8; nt++) {
                const int n = nt * 8 + r4;
                uint32_t bf[2];
                bf[0] = __float_as_uint(Vp[c * PV + n]);
                bf[1] = __float_as_uint(Vp[(c + 4) * PV + n]);
                mma_tf32(oacc[nt], af, bf);
            }
        }

        __syncthreads();
        if (kt + 2 <= qt) { issue_kv(cur, (kt + 2) * 64); cp_commit(); }
    }

    const float inv0 = 1.f / l0, inv1 = 1.f / l1;
    const int row0 = q0 + warp * 16 + r4;
    #pragma unroll
    for (int nt = 0; nt < 8; nt++) {
        const int col = h * HD + nt * 8 + 2 * c4;
        float2 o0, o1;
        o0.x = oacc[nt][0] * inv0; o0.y = oacc[nt][1] * inv0;
        o1.x = oacc[nt][2] * inv1; o1.y = oacc[nt][3] * inv1;
        *(float2*)(O + (size_t)(b * TD + row0) * CD + col)     = o0;
        *(float2*)(O + (size_t)(b * TD + row0 + 8) * CD + col) = o1;
    }
}

// ---------------------------------------------------------------------------
// Launch
// ---------------------------------------------------------------------------
extern "C" void kernel_launch(void* const* d_in, const int* in_sizes, int n_in,
                              void* d_out, int out_size)
{
    const float* x      = (const float*)d_in[0];
    const float* ln_a_g = (const float*)d_in[1];
    const float* ln_a_b = (const float*)d_in[2];
    const float* ln_b_g = (const float*)d_in[3];
    const float* ln_b_b = (const float*)d_in[4];
    const float* ln_c_g = (const float*)d_in[5];
    const float* ln_c_b = (const float*)d_in[6];
    const float* Wq = (const float*)d_in[7];  const float* bq = (const float*)d_in[8];
    const float* Wk = (const float*)d_in[9];  const float* bk = (const float*)d_in[10];
    const float* Wv = (const float*)d_in[11]; const float* bv = (const float*)d_in[12];
    const float* Wo = (const float*)d_in[13]; const float* bo = (const float*)d_in[14];
    const float* We = (const float*)d_in[15]; const float* be = (const float*)d_in[16];
    const float* Wd = (const float*)d_in[17]; const float* bd = (const float*)d_in[18];
    float* out = (float*)d_out;

    float *t, *q, *k, *v, *ctx, *x2, *h;
    cudaGetSymbolAddress((void**)&t,   g_t);
    cudaGetSymbolAddress((void**)&q,   g_q);
    cudaGetSymbolAddress((void**)&k,   g_k);
    cudaGetSymbolAddress((void**)&v,   g_v);
    cudaGetSymbolAddress((void**)&ctx, g_ctx);
    cudaGetSymbolAddress((void**)&x2,  g_x2);
    cudaGetSymbolAddress((void**)&h,   g_h);

    cudaFuncSetAttribute(attn_tc, cudaFuncAttributeMaxDynamicSharedMemorySize,
                         ATTN_SMEM);
    cudaFuncSetAttribute(attn_tc, cudaFuncAttributePreferredSharedMemoryCarveout,
                         100);

    // 1. t = LN_b(LN_a(x))
    ln2_kernel<<<NT, 256>>>(x, ln_a_g, ln_a_b, ln_b_g, ln_b_b, t);

    // 2. QKV projections — ONE fused launch, grid.z = 3
    {
        dim3 grid(CD / 128, NT / 128, 3);
        gemm_tc<<<grid, 256>>>(t, Wq, Wk, Wv, bq, bk, bv, nullptr,
                               q, k, v, NT, CD, CD, 0);
    }

    // 3. causal attention
    {
        dim3 grid(TD / 64, BD * HN);
        attn_tc<<<grid, 128, ATTN_SMEM>>>(q, k, v, ctx);
    }

    // 4. x2 = x + ctx @ Wo + bo
    {
        dim3 grid(CD / 128, NT / 128, 1);
        gemm_tc<<<grid, 256>>>(ctx, Wo, Wo, Wo, bo, bo, bo, x,
                               x2, x2, x2, NT, CD, CD, 0);
    }

    // 5. t = LN_c(x2)
    ln1_kernel<<<NT, 256>>>(x2, ln_c_g, ln_c_b, t);

    // 6. h = silu(t @ We + be)
    {
        dim3 grid(DFFD / 128, NT / 128, 1);
        gemm_tc<<<grid, 256>>>(t, We, We, We, be, be, be, nullptr,
                               h, h, h, NT, DFFD, CD, 1);
    }

    // 7. out = x2 + h @ Wd + bd
    {
        dim3 grid(CD / 128, NT / 128, 1);
        gemm_tc<<<grid, 256>>>(h, Wd, Wd, Wd, bd, bd, bd, x2,
                               out, out, out, NT, CD, DFFD, 0);
    }
}

// round 8
// speedup vs baseline: 1.8955x; 1.5265x over previous
#include <cuda_runtime.h>
#include <cuda_fp16.h>
#include <math.h>
#include <stdint.h>

// Problem dims
#define BD   2
#define TD   2048
#define CD   1024
#define HN   16
#define HD   64
#define DFFD 4096
#define NT   (BD * TD)   // 4096 tokens

// ---------------------------------------------------------------------------
// Scratch (device globals)
// ---------------------------------------------------------------------------
__device__ float  g_q  [(size_t)NT * CD];
__device__ float  g_k  [(size_t)NT * CD];
__device__ float  g_v  [(size_t)NT * CD];
__device__ float  g_x2 [(size_t)NT * CD];
__device__ __half g_th  [(size_t)NT * CD];    // ln2 out (fp16)
__device__ __half g_t2h [(size_t)NT * CD];    // ln1 out (fp16)
__device__ __half g_ctxh[(size_t)NT * CD];    // attn out (fp16)
__device__ __half g_hh  [(size_t)NT * DFFD];  // FFN hidden (fp16)
// k-pair-packed fp16 weights: word kk*N+n = {W[2kk][n], W[2kk+1][n]}
__device__ __half2 g_wqp[(CD/2) * CD];
__device__ __half2 g_wkp[(CD/2) * CD];
__device__ __half2 g_wvp[(CD/2) * CD];
__device__ __half2 g_wop[(CD/2) * CD];
__device__ __half2 g_wep[(CD/2) * DFFD];
__device__ __half2 g_wdp[(DFFD/2) * CD];

// ---------------------------------------------------------------------------
// Helpers
// ---------------------------------------------------------------------------
__device__ __forceinline__ void cp16(uint32_t smem_dst, const void* gptr) {
    asm volatile("cp.async.cg.shared.global [%0], [%1], 16;\n"
                 :: "r"(smem_dst), "l"(gptr));
}
__device__ __forceinline__ void cp_commit() {
    asm volatile("cp.async.commit_group;\n" ::: "memory");
}
template <int N>
__device__ __forceinline__ void cp_wait() {
    asm volatile("cp.async.wait_group %0;\n" :: "n"(N) : "memory");
}
__device__ __forceinline__ void mma_tf32(float* c, const uint32_t* a, const uint32_t* b) {
    asm volatile(
        "mma.sync.aligned.m16n8k8.row.col.f32.tf32.tf32.f32 "
        "{%0,%1,%2,%3},{%4,%5,%6,%7},{%8,%9},{%0,%1,%2,%3};"
        : "+f"(c[0]), "+f"(c[1]), "+f"(c[2]), "+f"(c[3])
        : "r"(a[0]), "r"(a[1]), "r"(a[2]), "r"(a[3]), "r"(b[0]), "r"(b[1]));
}
__device__ __forceinline__ void mma_f16(float* c, const uint32_t* a, const uint32_t* b) {
    asm volatile(
        "mma.sync.aligned.m16n8k16.row.col.f32.f16.f16.f32 "
        "{%0,%1,%2,%3},{%4,%5,%6,%7},{%8,%9},{%0,%1,%2,%3};"
        : "+f"(c[0]), "+f"(c[1]), "+f"(c[2]), "+f"(c[3])
        : "r"(a[0]), "r"(a[1]), "r"(a[2]), "r"(a[3]), "r"(b[0]), "r"(b[1]));
}

// ---------------------------------------------------------------------------
// Weight conversion: fp32 [K,N] -> k-pair-packed fp16 [(K/2)*N] half2
// ---------------------------------------------------------------------------
__global__ __launch_bounds__(256) void wconv(
    const float* __restrict__ W, __half2* __restrict__ out, int nshift)
{
    const int idx = blockIdx.x * 256 + threadIdx.x;
    const int kk = idx >> nshift;
    const int n  = idx & ((1 << nshift) - 1);
    const size_t base = ((size_t)(2 * kk) << nshift) + n;
    const float lo = W[base];
    const float hi = W[base + ((size_t)1 << nshift)];
    out[idx] = __floats2half2_rn(lo, hi);
}

// ---------------------------------------------------------------------------
// Fused double LayerNorm -> fp16 out
// ---------------------------------------------------------------------------
__global__ __launch_bounds__(256) void ln2_kernel(
    const float* __restrict__ x,
    const float* __restrict__ ga, const float* __restrict__ ba,
    const float* __restrict__ gb, const float* __restrict__ bb,
    __half* __restrict__ out)
{
    __shared__ float red[16];
    __shared__ float bc[2];
    const int row = blockIdx.x, tid = threadIdx.x;
    const float4 v = *(const float4*)(x + (size_t)row * CD + tid * 4);

    float s  = v.x + v.y + v.z + v.w;
    float s2 = v.x*v.x + v.y*v.y + v.z*v.z + v.w*v.w;
    #pragma unroll
    for (int o = 16; o; o >>= 1) {
        s  += __shfl_xor_sync(~0u, s,  o);
        s2 += __shfl_xor_sync(~0u, s2, o);
    }
    if ((tid & 31) == 0) { red[(tid >> 5)*2] = s; red[(tid >> 5)*2 + 1] = s2; }
    __syncthreads();
    if (tid == 0) {
        float a = 0.f, b2 = 0.f;
        #pragma unroll
        for (int w = 0; w < 8; w++) { a += red[w*2]; b2 += red[w*2 + 1]; }
        float mu  = a * (1.f / CD);
        float var = b2 * (1.f / CD) - mu * mu;
        bc[0] = mu; bc[1] = rsqrtf(var + 1e-5f);
    }
    __syncthreads();
    float mu = bc[0], rstd = bc[1];
    __syncthreads();

    const float4 g4 = *(const float4*)(ga + tid * 4);
    const float4 b4 = *(const float4*)(ba + tid * 4);
    float y[4];
    y[0] = (v.x - mu) * rstd * g4.x + b4.x;
    y[1] = (v.y - mu) * rstd * g4.y + b4.y;
    y[2] = (v.z - mu) * rstd * g4.z + b4.z;
    y[3] = (v.w - mu) * rstd * g4.w + b4.w;

    s  = y[0] + y[1] + y[2] + y[3];
    s2 = y[0]*y[0] + y[1]*y[1] + y[2]*y[2] + y[3]*y[3];
    #pragma unroll
    for (int o = 16; o; o >>= 1) {
        s  += __shfl_xor_sync(~0u, s,  o);
        s2 += __shfl_xor_sync(~0u, s2, o);
    }
    if ((tid & 31) == 0) { red[(tid >> 5)*2] = s; red[(tid >> 5)*2 + 1] = s2; }
    __syncthreads();
    if (tid == 0) {
        float a = 0.f, b2 = 0.f;
        #pragma unroll
        for (int w = 0; w < 8; w++) { a += red[w*2]; b2 += red[w*2 + 1]; }
        float mu2  = a * (1.f / CD);
        float var2 = b2 * (1.f / CD) - mu2 * mu2;
        bc[0] = mu2; bc[1] = rsqrtf(var2 + 1e-5f);
    }
    __syncthreads();
    mu = bc[0]; rstd = bc[1];

    const float4 g24 = *(const float4*)(gb + tid * 4);
    const float4 b24 = *(const float4*)(bb + tid * 4);
    float o0 = (y[0] - mu) * rstd * g24.x + b24.x;
    float o1 = (y[1] - mu) * rstd * g24.y + b24.y;
    float o2 = (y[2] - mu) * rstd * g24.z + b24.z;
    float o3 = (y[3] - mu) * rstd * g24.w + b24.w;
    __half* op = out + (size_t)row * CD + tid * 4;
    *(__half2*)(op)     = __floats2half2_rn(o0, o1);
    *(__half2*)(op + 2) = __floats2half2_rn(o2, o3);
}

__global__ __launch_bounds__(256) void ln1_kernel(
    const float* __restrict__ x,
    const float* __restrict__ g, const float* __restrict__ b,
    __half* __restrict__ out)
{
    __shared__ float red[16];
    __shared__ float bc[2];
    const int row = blockIdx.x, tid = threadIdx.x;
    const float4 v = *(const float4*)(x + (size_t)row * CD + tid * 4);

    float s  = v.x + v.y + v.z + v.w;
    float s2 = v.x*v.x + v.y*v.y + v.z*v.z + v.w*v.w;
    #pragma unroll
    for (int o = 16; o; o >>= 1) {
        s  += __shfl_xor_sync(~0u, s,  o);
        s2 += __shfl_xor_sync(~0u, s2, o);
    }
    if ((tid & 31) == 0) { red[(tid >> 5)*2] = s; red[(tid >> 5)*2 + 1] = s2; }
    __syncthreads();
    if (tid == 0) {
        float a = 0.f, b2 = 0.f;
        #pragma unroll
        for (int w = 0; w < 8; w++) { a += red[w*2]; b2 += red[w*2 + 1]; }
        float mu  = a * (1.f / CD);
        float var = b2 * (1.f / CD) - mu * mu;
        bc[0] = mu; bc[1] = rsqrtf(var + 1e-5f);
    }
    __syncthreads();
    const float mu = bc[0], rstd = bc[1];
    const float4 g4 = *(const float4*)(g + tid * 4);
    const float4 b4 = *(const float4*)(b + tid * 4);
    float o0 = (v.x - mu) * rstd * g4.x + b4.x;
    float o1 = (v.y - mu) * rstd * g4.y + b4.y;
    float o2 = (v.z - mu) * rstd * g4.z + b4.z;
    float o3 = (v.w - mu) * rstd * g4.w + b4.w;
    __half* op = out + (size_t)row * CD + tid * 4;
    *(__half2*)(op)     = __floats2half2_rn(o0, o1);
    *(__half2*)(op + 2) = __floats2half2_rn(o2, o3);
}

// ---------------------------------------------------------------------------
// FP16 tensor-core GEMM: 128x128 tile, BK=32 (2 x k16), 2-stage cp.async,
// 8 warps (2x4), warp 64x32, mma.m16n8k16.f16 with f32 accumulate.
//   A smem: [m][word] stride 20 words/row (16 data words = 32 halves), banks
//           (20m + c) bijective per fragment instruction.
//   B smem: [kk][n'] n' = n ^ (8*kk), 128 words/row (k-pair packed).
// grid.z selects weight set (fused QKV). Cc / Ch optional outputs.
// ---------------------------------------------------------------------------
__global__ __launch_bounds__(256, 2) void gemm_h(
    const __half* __restrict__ A,
    const __half2* __restrict__ Wp0, const __half2* __restrict__ Wp1,
    const __half2* __restrict__ Wp2,
    const float* __restrict__ b0, const float* __restrict__ b1,
    const float* __restrict__ b2,
    const float* __restrict__ res,
    float* __restrict__ C0, float* __restrict__ C1, float* __restrict__ C2,
    __half* __restrict__ Ch,
    int M, int N, int K, int act)
{
    __shared__ uint32_t As[2][128 * 20];   // 10 KB/stage
    __shared__ uint32_t Bs[2][16 * 128];   //  8 KB/stage

    const int z = blockIdx.z;
    const __half2* Wp  = (z == 0) ? Wp0 : (z == 1) ? Wp1 : Wp2;
    const float*  bias = (z == 0) ? b0  : (z == 1) ? b1  : b2;
    float*        Cc   = (z == 0) ? C0  : (z == 1) ? C1  : C2;

    const int tid  = threadIdx.x;
    const int lane = tid & 31;
    const int warp = tid >> 5;
    const int wm = warp & 1;
    const int wn = warp >> 1;
    const int bm = blockIdx.y * 128;
    const int bn = blockIdx.x * 128;

    // cp.async: A 512 chunks (2/thread), B 512 chunks (2/thread)
    const int ar1 = tid >> 2,          aq1 = tid & 3;
    const int ar2 = (tid + 256) >> 2,  aq2 = (tid + 256) & 3;
    const int bk1 = tid >> 5,          bn1 = tid & 31;
    const int bk2 = (tid + 256) >> 5,  bn2 = (tid + 256) & 31;

    const uint32_t sA = (uint32_t)__cvta_generic_to_shared(&As[0][0]);
    const uint32_t sB = (uint32_t)__cvta_generic_to_shared(&Bs[0][0]);
    const uint32_t aD1 = sA + (uint32_t)(ar1 * 20 + aq1 * 4) * 4u;
    const uint32_t aD2 = sA + (uint32_t)(ar2 * 20 + aq2 * 4) * 4u;
    const uint32_t bD1 = sB + (uint32_t)(bk1 * 128 + ((bn1 * 4) ^ (8 * bk1))) * 4u;
    const uint32_t bD2 = sB + (uint32_t)(bk2 * 128 + ((bn2 * 4) ^ (8 * bk2))) * 4u;

    const __half*  gA1 = A + (size_t)(bm + ar1) * K + aq1 * 8;
    const __half*  gA2 = A + (size_t)(bm + ar2) * K + aq2 * 8;
    const __half2* gB1 = Wp + (size_t)bk1 * N + bn + bn1 * 4;
    const __half2* gB2 = Wp + (size_t)bk2 * N + bn + bn2 * 4;
    const size_t bStep = (size_t)16 * N;

    float acc[4][4][4];
    #pragma unroll
    for (int i = 0; i < 4; i++)
        #pragma unroll
        for (int j = 0; j < 4; j++)
            #pragma unroll
            for (int r = 0; r < 4; r++) acc[i][j][r] = 0.f;

    auto issue = [&](uint32_t so) {
        cp16(aD1 + so * 10240u, gA1);
        cp16(aD2 + so * 10240u, gA2);
        cp16(bD1 + so * 8192u,  gB1);
        cp16(bD2 + so * 8192u,  gB2);
        gA1 += 32; gA2 += 32; gB1 += bStep; gB2 += bStep;
    };

    issue(0); cp_commit();
    issue(1); cp_commit();

    const int nK = K >> 5;
    const int r4 = lane >> 2;
    const int c4 = lane & 3;
    const int nb0 = wn * 32 + r4;   // base n for fragments

    for (int kt = 0; kt < nK; kt++) {
        cp_wait<1>();
        __syncthreads();
        const int cur = kt & 1;
        const uint32_t* Ap = &As[cur][0];
        const uint32_t* Bp = &Bs[cur][0];

        #pragma unroll
        for (int p = 0; p < 2; p++) {       // two k16 passes
            uint32_t af[4][4], bf[4][2];
            #pragma unroll
            for (int mf = 0; mf < 4; mf++) {
                const uint32_t* pr = Ap + (wm * 64 + mf * 16 + r4) * 20 + p * 8;
                af[mf][0] = pr[c4];
                af[mf][1] = pr[160 + c4];        // +8 rows
                af[mf][2] = pr[c4 + 4];
                af[mf][3] = pr[160 + c4 + 4];
            }
            #pragma unroll
            for (int nf = 0; nf < 4; nf++) {
                const int n = nb0 + nf * 8;
                bf[nf][0] = Bp[(p * 8 + c4) * 128     + (n ^ (64 * p + 8 * c4))];
                bf[nf][1] = Bp[(p * 8 + c4 + 4) * 128 + (n ^ (64 * p + 8 * c4 + 32))];
            }
            #pragma unroll
            for (int mf = 0; mf < 4; mf++)
                #pragma unroll
                for (int nf = 0; nf < 4; nf++)
                    mma_f16(acc[mf][nf], af[mf], bf[nf]);
        }
        __syncthreads();
        if (kt + 2 < nK) issue(cur);
        cp_commit();
    }

    // epilogue
    #pragma unroll
    for (int mf = 0; mf < 4; mf++) {
        #pragma unroll
        for (int nf = 0; nf < 4; nf++) {
            const int col = bn + wn * 32 + nf * 8 + c4 * 2;
            const float bx = bias[col], by = bias[col + 1];
            #pragma unroll
            for (int h = 0; h < 2; h++) {
                const int row = bm + wm * 64 + mf * 16 + r4 + h * 8;
                float ox = acc[mf][nf][h * 2 + 0] + bx;
                float oy = acc[mf][nf][h * 2 + 1] + by;
                if (act) {
                    ox *= 1.f / (1.f + __expf(-ox));
                    oy *= 1.f / (1.f + __expf(-oy));
                }
                const size_t off = (size_t)row * N + col;
                if (res) {
                    const float2 rr = *(const float2*)(res + off);
                    ox += rr.x; oy += rr.y;
                }
                if (Cc) {
                    float2 o; o.x = ox; o.y = oy;
                    *(float2*)(Cc + off) = o;
                }
                if (Ch) *(__half2*)(Ch + off) = __floats2half2_rn(ox, oy);
            }
        }
    }
}

// ---------------------------------------------------------------------------
// Flash attention on tensor cores (tf32, fp32 in; fp16 out for Wo GEMM)
// ---------------------------------------------------------------------------
#define PQ 68
#define PV 72
#define ATTN_SMEM ((64*PQ + 2*64*PQ + 2*64*PV + 4*16*PQ) * 4)

__global__ __launch_bounds__(128) void attn_tc(
    const float* __restrict__ Q, const float* __restrict__ Kg,
    const float* __restrict__ Vg, __half* __restrict__ O)
{
    extern __shared__ float sm[];
    float* Qs = sm;
    float* Ks = Qs + 64 * PQ;
    float* Vs = Ks + 2 * 64 * PQ;
    float* Ps = Vs + 2 * 64 * PV;

    const int bh = blockIdx.y;
    const int b = bh >> 4, h = bh & 15;
    const int qt = blockIdx.x;
    const int q0 = qt * 64;
    const int tid = threadIdx.x;
    const int lane = tid & 31;
    const int warp = tid >> 5;
    const int r4 = lane >> 2;
    const int c4 = lane & 3;
    const size_t base = (size_t)b * TD * CD + (size_t)h * HD;

    const uint32_t sQ = (uint32_t)__cvta_generic_to_shared(Qs);
    const uint32_t sK = (uint32_t)__cvta_generic_to_shared(Ks);
    const uint32_t sV = (uint32_t)__cvta_generic_to_shared(Vs);

    #pragma unroll
    for (int i = 0; i < 8; i++) {
        const int idx = tid + i * 128;
        const int row = idx >> 4, cc = idx & 15;
        cp16(sQ + (uint32_t)(row * PQ + cc * 4) * 4u,
             Q + base + (size_t)(q0 + row) * CD + cc * 4);
    }
    auto issue_kv = [&](int buf, int k0) {
        #pragma unroll
        for (int i = 0; i < 8; i++) {
            const int idx = tid + i * 128;
            const int row = idx >> 4, cc = idx & 15;
            const size_t g = base + (size_t)(k0 + row) * CD + cc * 4;
            cp16(sK + (uint32_t)(buf * 64 * PQ + row * PQ + cc * 4) * 4u, Kg + g);
            cp16(sV + (uint32_t)(buf * 64 * PV + row * PV + cc * 4) * 4u, Vg + g);
        }
    };
    issue_kv(0, 0);
    cp_commit();
    if (qt >= 1) { issue_kv(1, 64); cp_commit(); }

    uint32_t qf[8][4];
    float oacc[8][4];
    #pragma unroll
    for (int nt = 0; nt < 8; nt++)
        #pragma unroll
        for (int r = 0; r < 4; r++) oacc[nt][r] = 0.f;
    float m0 = -1e30f, m1 = -1e30f, l0 = 0.f, l1 = 0.f;

    float* Pw = Ps + warp * 16 * PQ;

    for (int kt = 0; kt <= qt; kt++) {
        if (kt + 1 <= qt) cp_wait<1>(); else cp_wait<0>();
        __syncthreads();
        const int cur = kt & 1;
        const float* Kp = Ks + cur * 64 * PQ;
        const float* Vp = Vs + cur * 64 * PV;

        if (kt == 0) {
            const float* qp = Qs + (warp * 16 + r4) * PQ;
            #pragma unroll
            for (int ks = 0; ks < 8; ks++) {
                const int c = ks * 8 + c4;
                qf[ks][0] = __float_as_uint(qp[c] * 0.125f);
                qf[ks][1] = __float_as_uint(qp[8 * PQ + c] * 0.125f);
                qf[ks][2] = __float_as_uint(qp[c + 4] * 0.125f);
                qf[ks][3] = __float_as_uint(qp[8 * PQ + c + 4] * 0.125f);
            }
        }

        float sacc[8][4];
        #pragma unroll
        for (int nt = 0; nt < 8; nt++)
            #pragma unroll
            for (int r = 0; r < 4; r++) sacc[nt][r] = 0.f;

        #pragma unroll
        for (int ks = 0; ks < 8; ks++) {
            const int k = ks * 8 + c4;
            #pragma unroll
            for (int nt = 0; nt < 8; nt++) {
                const int n = nt * 8 + r4;
                uint32_t bf[2];
                bf[0] = __float_as_uint(Kp[n * PQ + k]);
                bf[1] = __float_as_uint(Kp[n * PQ + k + 4]);
                mma_tf32(sacc[nt], qf[ks], bf);
            }
        }

        if (kt == qt) {
            const int row0 = warp * 16 + r4;
            #pragma unroll
            for (int nt = 0; nt < 8; nt++) {
                const int cb = nt * 8 + 2 * c4;
                if (cb + 0 > row0)     sacc[nt][0] = -1e30f;
                if (cb + 1 > row0)     sacc[nt][1] = -1e30f;
                if (cb + 0 > row0 + 8) sacc[nt][2] = -1e30f;
                if (cb + 1 > row0 + 8) sacc[nt][3] = -1e30f;
            }
        }

        float rm0 = -1e30f, rm1 = -1e30f;
        #pragma unroll
        for (int nt = 0; nt < 8; nt++) {
            rm0 = fmaxf(rm0, fmaxf(sacc[nt][0], sacc[nt][1]));
            rm1 = fmaxf(rm1, fmaxf(sacc[nt][2], sacc[nt][3]));
        }
        rm0 = fmaxf(rm0, __shfl_xor_sync(~0u, rm0, 1));
        rm0 = fmaxf(rm0, __shfl_xor_sync(~0u, rm0, 2));
        rm1 = fmaxf(rm1, __shfl_xor_sync(~0u, rm1, 1));
        rm1 = fmaxf(rm1, __shfl_xor_sync(~0u, rm1, 2));

        const float mn0 = fmaxf(m0, rm0), mn1 = fmaxf(m1, rm1);
        const float f0 = __expf(m0 - mn0), f1 = __expf(m1 - mn1);
        m0 = mn0; m1 = mn1;

        float rs0 = 0.f, rs1 = 0.f;
        #pragma unroll
        for (int nt = 0; nt < 8; nt++) {
            float p0 = __expf(sacc[nt][0] - mn0);
            float p1 = __expf(sacc[nt][1] - mn0);
            float p2 = __expf(sacc[nt][2] - mn1);
            float p3 = __expf(sacc[nt][3] - mn1);
            rs0 += p0 + p1; rs1 += p2 + p3;
            float2 w0; w0.x = p0; w0.y = p1;
            float2 w1; w1.x = p2; w1.y = p3;
            *(float2*)(Pw + r4 * PQ + nt * 8 + 2 * c4)       = w0;
            *(float2*)(Pw + (r4 + 8) * PQ + nt * 8 + 2 * c4) = w1;
        }
        rs0 += __shfl_xor_sync(~0u, rs0, 1);
        rs0 += __shfl_xor_sync(~0u, rs0, 2);
        rs1 += __shfl_xor_sync(~0u, rs1, 1);
        rs1 += __shfl_xor_sync(~0u, rs1, 2);
        l0 = l0 * f0 + rs0;
        l1 = l1 * f1 + rs1;

        #pragma unroll
        for (int nt = 0; nt < 8; nt++) {
            oacc[nt][0] *= f0; oacc[nt][1] *= f0;
            oacc[nt][2] *= f1; oacc[nt][3] *= f1;
        }
        __syncwarp();

        #pragma unroll
        for (int ks = 0; ks < 8; ks++) {
            const int c = ks * 8 + c4;
            uint32_t af[4];
            af[0] = __float_as_uint(Pw[r4 * PQ + c]);
            af[1] = __float_as_uint(Pw[(r4 + 8) * PQ + c]);
            af[2] = __float_as_uint(Pw[r4 * PQ + c + 4]);
            af[3] = __float_as_uint(Pw[(r4 + 8) * PQ + c + 4]);
            #pragma unroll
            for (int nt = 0; nt < 8; nt++) {
                const int n = nt * 8 + r4;
                uint32_t bf[2];
                bf[0] = __float_as_uint(Vp[c * PV + n]);
                bf[1] = __float_as_uint(Vp[(c + 4) * PV + n]);
                mma_tf32(oacc[nt], af, bf);
            }
        }

        __syncthreads();
        if (kt + 2 <= qt) { issue_kv(cur, (kt + 2) * 64); cp_commit(); }
    }

    const float inv0 = 1.f / l0, inv1 = 1.f / l1;
    const int row0 = q0 + warp * 16 + r4;
    #pragma unroll
    for (int nt = 0; nt < 8; nt++) {
        const int col = h * HD + nt * 8 + 2 * c4;
        *(__half2*)(O + (size_t)(b * TD + row0) * CD + col) =
            __floats2half2_rn(oacc[nt][0] * inv0, oacc[nt][1] * inv0);
        *(__half2*)(O + (size_t)(b * TD + row0 + 8) * CD + col) =
            __floats2half2_rn(oacc[nt][2] * inv1, oacc[nt][3] * inv1);
    }
}

// ---------------------------------------------------------------------------
// Launch
// ---------------------------------------------------------------------------
extern "C" void kernel_launch(void* const* d_in, const int* in_sizes, int n_in,
                              void* d_out, int out_size)
{
    const float* x      = (const float*)d_in[0];
    const float* ln_a_g = (const float*)d_in[1];
    const float* ln_a_b = (const float*)d_in[2];
    const float* ln_b_g = (const float*)d_in[3];
    const float* ln_b_b = (const float*)d_in[4];
    const float* ln_c_g = (const float*)d_in[5];
    const float* ln_c_b = (const float*)d_in[6];
    const float* Wq = (const float*)d_in[7];  const float* bq = (const float*)d_in[8];
    const float* Wk = (const float*)d_in[9];  const float* bk = (const float*)d_in[10];
    const float* Wv = (const float*)d_in[11]; const float* bv = (const float*)d_in[12];
    const float* Wo = (const float*)d_in[13]; const float* bo = (const float*)d_in[14];
    const float* We = (const float*)d_in[15]; const float* be = (const float*)d_in[16];
    const float* Wd = (const float*)d_in[17]; const float* bd = (const float*)d_in[18];
    float* out = (float*)d_out;

    float *q, *k, *v, *x2;
    __half *th, *t2h, *ctxh, *hh;
    __half2 *wqp, *wkp, *wvp, *wop, *wep, *wdp;
    cudaGetSymbolAddress((void**)&q,    g_q);
    cudaGetSymbolAddress((void**)&k,    g_k);
    cudaGetSymbolAddress((void**)&v,    g_v);
    cudaGetSymbolAddress((void**)&x2,   g_x2);
    cudaGetSymbolAddress((void**)&th,   g_th);
    cudaGetSymbolAddress((void**)&t2h,  g_t2h);
    cudaGetSymbolAddress((void**)&ctxh, g_ctxh);
    cudaGetSymbolAddress((void**)&hh,   g_hh);
    cudaGetSymbolAddress((void**)&wqp,  g_wqp);
    cudaGetSymbolAddress((void**)&wkp,  g_wkp);
    cudaGetSymbolAddress((void**)&wvp,  g_wvp);
    cudaGetSymbolAddress((void**)&wop,  g_wop);
    cudaGetSymbolAddress((void**)&wep,  g_wep);
    cudaGetSymbolAddress((void**)&wdp,  g_wdp);

    cudaFuncSetAttribute(attn_tc, cudaFuncAttributeMaxDynamicSharedMemorySize,
                         ATTN_SMEM);
    cudaFuncSetAttribute(attn_tc, cudaFuncAttributePreferredSharedMemoryCarveout,
                         100);

    // 0. weight conversion to k-pair-packed fp16
    wconv<<<(CD/2)*CD/256,   256>>>(Wq, wqp, 10);
    wconv<<<(CD/2)*CD/256,   256>>>(Wk, wkp, 10);
    wconv<<<(CD/2)*CD/256,   256>>>(Wv, wvp, 10);
    wconv<<<(CD/2)*CD/256,   256>>>(Wo, wop, 10);
    wconv<<<(CD/2)*DFFD/256, 256>>>(We, wep, 12);
    wconv<<<(DFFD/2)*CD/256, 256>>>(Wd, wdp, 10);

    // 1. th = fp16(LN_b(LN_a(x)))
    ln2_kernel<<<NT, 256>>>(x, ln_a_g, ln_a_b, ln_b_g, ln_b_b, th);

    // 2. QKV projections (fused, fp16 mma)
    {
        dim3 grid(CD / 128, NT / 128, 3);
        gemm_h<<<grid, 256>>>(th, wqp, wkp, wvp, bq, bk, bv, nullptr,
                              q, k, v, nullptr, NT, CD, CD, 0);
    }

    // 3. causal attention -> ctxh (fp16)
    {
        dim3 grid(TD / 64, BD * HN);
        attn_tc<<<grid, 128, ATTN_SMEM>>>(q, k, v, ctxh);
    }

    // 4. x2 = x + ctx @ Wo + bo
    {
        dim3 grid(CD / 128, NT / 128, 1);
        gemm_h<<<grid, 256>>>(ctxh, wop, wop, wop, bo, bo, bo, x,
                              x2, x2, x2, nullptr, NT, CD, CD, 0);
    }

    // 5. t2h = fp16(LN_c(x2))
    ln1_kernel<<<NT, 256>>>(x2, ln_c_g, ln_c_b, t2h);

    // 6. hh = fp16(silu(t2 @ We + be))   (fp16 output only)
    {
        dim3 grid(DFFD / 128, NT / 128, 1);
        gemm_h<<<grid, 256>>>(t2h, wep, wep, wep, be, be, be, nullptr,
                              nullptr, nullptr, nullptr, hh, NT, DFFD, CD, 1);
    }

    // 7. out = x2 + h @ Wd + bd
    {
        dim3 grid(CD / 128, NT / 128, 1);
        gemm_h<<<grid, 256>>>(hh, wdp, wdp, wdp, bd, bd, bd, x2,
                              out, out, out, nullptr, NT, CD, DFFD, 0);
    }
}

// round 9
// speedup vs baseline: 2.2425x; 1.1831x over previous
#include <cuda_runtime.h>
#include <cuda_fp16.h>
#include <math.h>
#include <stdint.h>

// Problem dims
#define BD   2
#define TD   2048
#define CD   1024
#define HN   16
#define HD   64
#define DFFD 4096
#define NT   (BD * TD)   // 4096 tokens

// ---------------------------------------------------------------------------
// Scratch (device globals)
// ---------------------------------------------------------------------------
__device__ float  g_x2 [(size_t)NT * CD];
__device__ __half g_th  [(size_t)NT * CD];    // ln2 out
__device__ __half g_t2h [(size_t)NT * CD];    // ln1 out
__device__ __half g_qh  [(size_t)NT * CD];
__device__ __half g_kh  [(size_t)NT * CD];
__device__ __half g_vt  [(size_t)CD * NT];    // V transposed [dim][token]
__device__ __half g_ctxh[(size_t)NT * CD];
__device__ __half g_hh  [(size_t)NT * DFFD];
// k-pair-packed fp16 weights
__device__ __half2 g_wqp[(CD/2) * CD];
__device__ __half2 g_wkp[(CD/2) * CD];
__device__ __half2 g_wvp[(CD/2) * CD];
__device__ __half2 g_wop[(CD/2) * CD];
__device__ __half2 g_wep[(CD/2) * DFFD];
__device__ __half2 g_wdp[(DFFD/2) * CD];

// ---------------------------------------------------------------------------
// Helpers
// ---------------------------------------------------------------------------
__device__ __forceinline__ void cp16(uint32_t smem_dst, const void* gptr) {
    asm volatile("cp.async.cg.shared.global [%0], [%1], 16;\n"
                 :: "r"(smem_dst), "l"(gptr));
}
__device__ __forceinline__ void cp_commit() {
    asm volatile("cp.async.commit_group;\n" ::: "memory");
}
template <int N>
__device__ __forceinline__ void cp_wait() {
    asm volatile("cp.async.wait_group %0;\n" :: "n"(N) : "memory");
}
__device__ __forceinline__ void mma_f16(float* c, const uint32_t* a, const uint32_t* b) {
    asm volatile(
        "mma.sync.aligned.m16n8k16.row.col.f32.f16.f16.f32 "
        "{%0,%1,%2,%3},{%4,%5,%6,%7},{%8,%9},{%0,%1,%2,%3};"
        : "+f"(c[0]), "+f"(c[1]), "+f"(c[2]), "+f"(c[3])
        : "r"(a[0]), "r"(a[1]), "r"(a[2]), "r"(a[3]), "r"(b[0]), "r"(b[1]));
}
__device__ __forceinline__ uint32_t h2scale(uint32_t w, __half2 s) {
    __half2 a = *(__half2*)&w;
    a = __hmul2(a, s);
    return *(uint32_t*)&a;
}

// ---------------------------------------------------------------------------
// Weight conversion: fp32 [K,N] -> k-pair-packed fp16 [(K/2)*N] half2
// ---------------------------------------------------------------------------
__global__ __launch_bounds__(256) void wconv(
    const float* __restrict__ W, __half2* __restrict__ out, int nshift)
{
    const int idx = blockIdx.x * 256 + threadIdx.x;
    const int kk = idx >> nshift;
    const int n  = idx & ((1 << nshift) - 1);
    const size_t base = ((size_t)(2 * kk) << nshift) + n;
    const float lo = W[base];
    const float hi = W[base + ((size_t)1 << nshift)];
    out[idx] = __floats2half2_rn(lo, hi);
}

// ---------------------------------------------------------------------------
// Fused double LayerNorm -> fp16 out
// ---------------------------------------------------------------------------
__global__ __launch_bounds__(256) void ln2_kernel(
    const float* __restrict__ x,
    const float* __restrict__ ga, const float* __restrict__ ba,
    const float* __restrict__ gb, const float* __restrict__ bb,
    __half* __restrict__ out)
{
    __shared__ float red[16];
    __shared__ float bc[2];
    const int row = blockIdx.x, tid = threadIdx.x;
    const float4 v = *(const float4*)(x + (size_t)row * CD + tid * 4);

    float s  = v.x + v.y + v.z + v.w;
    float s2 = v.x*v.x + v.y*v.y + v.z*v.z + v.w*v.w;
    #pragma unroll
    for (int o = 16; o; o >>= 1) {
        s  += __shfl_xor_sync(~0u, s,  o);
        s2 += __shfl_xor_sync(~0u, s2, o);
    }
    if ((tid & 31) == 0) { red[(tid >> 5)*2] = s; red[(tid >> 5)*2 + 1] = s2; }
    __syncthreads();
    if (tid == 0) {
        float a = 0.f, b2 = 0.f;
        #pragma unroll
        for (int w = 0; w < 8; w++) { a += red[w*2]; b2 += red[w*2 + 1]; }
        float mu  = a * (1.f / CD);
        float var = b2 * (1.f / CD) - mu * mu;
        bc[0] = mu; bc[1] = rsqrtf(var + 1e-5f);
    }
    __syncthreads();
    float mu = bc[0], rstd = bc[1];
    __syncthreads();

    const float4 g4 = *(const float4*)(ga + tid * 4);
    const float4 b4 = *(const float4*)(ba + tid * 4);
    float y[4];
    y[0] = (v.x - mu) * rstd * g4.x + b4.x;
    y[1] = (v.y - mu) * rstd * g4.y + b4.y;
    y[2] = (v.z - mu) * rstd * g4.z + b4.z;
    y[3] = (v.w - mu) * rstd * g4.w + b4.w;

    s  = y[0] + y[1] + y[2] + y[3];
    s2 = y[0]*y[0] + y[1]*y[1] + y[2]*y[2] + y[3]*y[3];
    #pragma unroll
    for (int o = 16; o; o >>= 1) {
        s  += __shfl_xor_sync(~0u, s,  o);
        s2 += __shfl_xor_sync(~0u, s2, o);
    }
    if ((tid & 31) == 0) { red[(tid >> 5)*2] = s; red[(tid >> 5)*2 + 1] = s2; }
    __syncthreads();
    if (tid == 0) {
        float a = 0.f, b2 = 0.f;
        #pragma unroll
        for (int w = 0; w < 8; w++) { a += red[w*2]; b2 += red[w*2 + 1]; }
        float mu2  = a * (1.f / CD);
        float var2 = b2 * (1.f / CD) - mu2 * mu2;
        bc[0] = mu2; bc[1] = rsqrtf(var2 + 1e-5f);
    }
    __syncthreads();
    mu = bc[0]; rstd = bc[1];

    const float4 g24 = *(const float4*)(gb + tid * 4);
    const float4 b24 = *(const float4*)(bb + tid * 4);
    float o0 = (y[0] - mu) * rstd * g24.x + b24.x;
    float o1 = (y[1] - mu) * rstd * g24.y + b24.y;
    float o2 = (y[2] - mu) * rstd * g24.z + b24.z;
    float o3 = (y[3] - mu) * rstd * g24.w + b24.w;
    __half* op = out + (size_t)row * CD + tid * 4;
    *(__half2*)(op)     = __floats2half2_rn(o0, o1);
    *(__half2*)(op + 2) = __floats2half2_rn(o2, o3);
}

__global__ __launch_bounds__(256) void ln1_kernel(
    const float* __restrict__ x,
    const float* __restrict__ g, const float* __restrict__ b,
    __half* __restrict__ out)
{
    __shared__ float red[16];
    __shared__ float bc[2];
    const int row = blockIdx.x, tid = threadIdx.x;
    const float4 v = *(const float4*)(x + (size_t)row * CD + tid * 4);

    float s  = v.x + v.y + v.z + v.w;
    float s2 = v.x*v.x + v.y*v.y + v.z*v.z + v.w*v.w;
    #pragma unroll
    for (int o = 16; o; o >>= 1) {
        s  += __shfl_xor_sync(~0u, s,  o);
        s2 += __shfl_xor_sync(~0u, s2, o);
    }
    if ((tid & 31) == 0) { red[(tid >> 5)*2] = s; red[(tid >> 5)*2 + 1] = s2; }
    __syncthreads();
    if (tid == 0) {
        float a = 0.f, b2 = 0.f;
        #pragma unroll
        for (int w = 0; w < 8; w++) { a += red[w*2]; b2 += red[w*2 + 1]; }
        float mu  = a * (1.f / CD);
        float var = b2 * (1.f / CD) - mu * mu;
        bc[0] = mu; bc[1] = rsqrtf(var + 1e-5f);
    }
    __syncthreads();
    const float mu = bc[0], rstd = bc[1];
    const float4 g4 = *(const float4*)(g + tid * 4);
    const float4 b4 = *(const float4*)(b + tid * 4);
    float o0 = (v.x - mu) * rstd * g4.x + b4.x;
    float o1 = (v.y - mu) * rstd * g4.y + b4.y;
    float o2 = (v.z - mu) * rstd * g4.z + b4.z;
    float o3 = (v.w - mu) * rstd * g4.w + b4.w;
    __half* op = out + (size_t)row * CD + tid * 4;
    *(__half2*)(op)     = __floats2half2_rn(o0, o1);
    *(__half2*)(op + 2) = __floats2half2_rn(o2, o3);
}

// ---------------------------------------------------------------------------
// FP16 tensor-core GEMM (same core as R8). Outputs per z:
//   C0..C2: fp32 (optional), H0..H2: fp16 (optional).
//   If vtz2 and z==2: H2 written TRANSPOSED as [col][row] (for V).
// ---------------------------------------------------------------------------
__global__ __launch_bounds__(256, 2) void gemm_h(
    const __half* __restrict__ A,
    const __half2* __restrict__ Wp0, const __half2* __restrict__ Wp1,
    const __half2* __restrict__ Wp2,
    const float* __restrict__ b0, const float* __restrict__ b1,
    const float* __restrict__ b2,
    const float* __restrict__ res,
    float* __restrict__ C0, float* __restrict__ C1, float* __restrict__ C2,
    __half* __restrict__ H0, __half* __restrict__ H1, __half* __restrict__ H2,
    int vtz2, int M, int N, int K, int act)
{
    __shared__ uint32_t As[2][128 * 20];
    __shared__ uint32_t Bs[2][16 * 128];

    const int z = blockIdx.z;
    const __half2* Wp  = (z == 0) ? Wp0 : (z == 1) ? Wp1 : Wp2;
    const float*  bias = (z == 0) ? b0  : (z == 1) ? b1  : b2;
    float*        Cc   = (z == 0) ? C0  : (z == 1) ? C1  : C2;
    __half*       Hh   = (z == 0) ? H0  : (z == 1) ? H1  : H2;
    const bool    vt   = (z == 2) && vtz2;

    const int tid  = threadIdx.x;
    const int lane = tid & 31;
    const int warp = tid >> 5;
    const int wm = warp & 1;
    const int wn = warp >> 1;
    const int bm = blockIdx.y * 128;
    const int bn = blockIdx.x * 128;

    const int ar1 = tid >> 2,          aq1 = tid & 3;
    const int ar2 = (tid + 256) >> 2,  aq2 = (tid + 256) & 3;
    const int bk1 = tid >> 5,          bn1 = tid & 31;
    const int bk2 = (tid + 256) >> 5,  bn2 = (tid + 256) & 31;

    const uint32_t sA = (uint32_t)__cvta_generic_to_shared(&As[0][0]);
    const uint32_t sB = (uint32_t)__cvta_generic_to_shared(&Bs[0][0]);
    const uint32_t aD1 = sA + (uint32_t)(ar1 * 20 + aq1 * 4) * 4u;
    const uint32_t aD2 = sA + (uint32_t)(ar2 * 20 + aq2 * 4) * 4u;
    const uint32_t bD1 = sB + (uint32_t)(bk1 * 128 + ((bn1 * 4) ^ (8 * bk1))) * 4u;
    const uint32_t bD2 = sB + (uint32_t)(bk2 * 128 + ((bn2 * 4) ^ (8 * bk2))) * 4u;

    const __half*  gA1 = A + (size_t)(bm + ar1) * K + aq1 * 8;
    const __half*  gA2 = A + (size_t)(bm + ar2) * K + aq2 * 8;
    const __half2* gB1 = Wp + (size_t)bk1 * N + bn + bn1 * 4;
    const __half2* gB2 = Wp + (size_t)bk2 * N + bn + bn2 * 4;
    const size_t bStep = (size_t)16 * N;

    float acc[4][4][4];
    #pragma unroll
    for (int i = 0; i < 4; i++)
        #pragma unroll
        for (int j = 0; j < 4; j++)
            #pragma unroll
            for (int r = 0; r < 4; r++) acc[i][j][r] = 0.f;

    auto issue = [&](uint32_t so) {
        cp16(aD1 + so * 10240u, gA1);
        cp16(aD2 + so * 10240u, gA2);
        cp16(bD1 + so * 8192u,  gB1);
        cp16(bD2 + so * 8192u,  gB2);
        gA1 += 32; gA2 += 32; gB1 += bStep; gB2 += bStep;
    };

    issue(0); cp_commit();
    issue(1); cp_commit();

    const int nK = K >> 5;
    const int r4 = lane >> 2;
    const int c4 = lane & 3;
    const int nb0 = wn * 32 + r4;

    for (int kt = 0; kt < nK; kt++) {
        cp_wait<1>();
        __syncthreads();
        const int cur = kt & 1;
        const uint32_t* Ap = &As[cur][0];
        const uint32_t* Bp = &Bs[cur][0];

        #pragma unroll
        for (int p = 0; p < 2; p++) {
            uint32_t af[4][4], bf[4][2];
            #pragma unroll
            for (int mf = 0; mf < 4; mf++) {
                const uint32_t* pr = Ap + (wm * 64 + mf * 16 + r4) * 20 + p * 8;
                af[mf][0] = pr[c4];
                af[mf][1] = pr[160 + c4];
                af[mf][2] = pr[c4 + 4];
                af[mf][3] = pr[160 + c4 + 4];
            }
            #pragma unroll
            for (int nf = 0; nf < 4; nf++) {
                const int n = nb0 + nf * 8;
                bf[nf][0] = Bp[(p * 8 + c4) * 128     + (n ^ (64 * p + 8 * c4))];
                bf[nf][1] = Bp[(p * 8 + c4 + 4) * 128 + (n ^ (64 * p + 8 * c4 + 32))];
            }
            #pragma unroll
            for (int mf = 0; mf < 4; mf++)
                #pragma unroll
                for (int nf = 0; nf < 4; nf++)
                    mma_f16(acc[mf][nf], af[mf], bf[nf]);
        }
        __syncthreads();
        if (kt + 2 < nK) issue(cur);
        cp_commit();
    }

    // epilogue
    #pragma unroll
    for (int mf = 0; mf < 4; mf++) {
        #pragma unroll
        for (int nf = 0; nf < 4; nf++) {
            const int col = bn + wn * 32 + nf * 8 + c4 * 2;
            const float bx = bias[col], by = bias[col + 1];
            #pragma unroll
            for (int h = 0; h < 2; h++) {
                const int row = bm + wm * 64 + mf * 16 + r4 + h * 8;
                float ox = acc[mf][nf][h * 2 + 0] + bx;
                float oy = acc[mf][nf][h * 2 + 1] + by;
                if (act) {
                    ox *= 1.f / (1.f + __expf(-ox));
                    oy *= 1.f / (1.f + __expf(-oy));
                }
                const size_t off = (size_t)row * N + col;
                if (res) {
                    const float2 rr = *(const float2*)(res + off);
                    ox += rr.x; oy += rr.y;
                }
                if (Cc) {
                    float2 o; o.x = ox; o.y = oy;
                    *(float2*)(Cc + off) = o;
                }
                if (Hh) {
                    if (vt) {
                        Hh[(size_t)col * M + row]       = __float2half(ox);
                        Hh[(size_t)(col + 1) * M + row] = __float2half(oy);
                    } else {
                        *(__half2*)(Hh + off) = __floats2half2_rn(ox, oy);
                    }
                }
            }
        }
    }
}

// ---------------------------------------------------------------------------
// FP16 flash attention. Q/K: [token][C] fp16; V: transposed [dim][token] fp16.
// Grid (T/64, B*H), 128 threads. All smem stride 36 words (bank-bijective).
// ---------------------------------------------------------------------------
#define AST 36
#define ATTN_SMEM ((64*AST + 2*64*AST + 2*64*AST + 4*16*AST) * 4)  // 55296 B

__global__ __launch_bounds__(128) void attn_h(
    const __half* __restrict__ Qh, const __half* __restrict__ Kh,
    const __half* __restrict__ Vt, __half* __restrict__ O)
{
    extern __shared__ uint32_t sm[];
    uint32_t* Qs = sm;                    // [64][36]
    uint32_t* Ks = Qs + 64 * AST;         // [2][64][36]
    uint32_t* Vs = Ks + 2 * 64 * AST;     // [2][64][36]  ([dim][key-pair])
    uint32_t* Ps = Vs + 2 * 64 * AST;     // [4][16][36]

    const int bh = blockIdx.y;
    const int b = bh >> 4, h = bh & 15;
    const int qt = blockIdx.x;
    const int q0 = qt * 64;
    const int tid = threadIdx.x;
    const int lane = tid & 31;
    const int warp = tid >> 5;
    const int r4 = lane >> 2;
    const int c4 = lane & 3;

    const __half* qg = Qh + (size_t)(b * TD + q0) * CD + h * HD;
    const __half* kg = Kh + (size_t)b * TD * CD + h * HD;
    const __half* vg = Vt + (size_t)(h * HD) * NT + b * TD;

    const uint32_t sQ = (uint32_t)__cvta_generic_to_shared(Qs);
    const uint32_t sK = (uint32_t)__cvta_generic_to_shared(Ks);
    const uint32_t sV = (uint32_t)__cvta_generic_to_shared(Vs);

    // Q: 64 rows x 128B = 512 chunks
    #pragma unroll
    for (int i = 0; i < 4; i++) {
        const int idx = tid + i * 128;
        const int row = idx >> 3, cc = idx & 7;
        cp16(sQ + (uint32_t)(row * AST + cc * 4) * 4u, qg + row * CD + cc * 8);
    }
    auto issue_kv = [&](int buf, int k0) {
        #pragma unroll
        for (int i = 0; i < 4; i++) {
            const int idx = tid + i * 128;
            const int row = idx >> 3, cc = idx & 7;
            cp16(sK + (uint32_t)(buf * 64 * AST + row * AST + cc * 4) * 4u,
                 kg + (size_t)(k0 + row) * CD + cc * 8);
            cp16(sV + (uint32_t)(buf * 64 * AST + row * AST + cc * 4) * 4u,
                 vg + (size_t)row * NT + k0 + cc * 8);
        }
    };
    issue_kv(0, 0);
    cp_commit();
    if (qt >= 1) { issue_kv(1, 64); cp_commit(); }

    uint32_t qf[4][4];
    float oacc[8][4];
    #pragma unroll
    for (int nt = 0; nt < 8; nt++)
        #pragma unroll
        for (int r = 0; r < 4; r++) oacc[nt][r] = 0.f;
    float m0 = -1e30f, m1 = -1e30f, l0 = 0.f, l1 = 0.f;

    uint32_t* Pw = Ps + warp * 16 * AST;
    const __half2 sc = __float2half2_rn(0.125f);

    for (int kt = 0; kt <= qt; kt++) {
        if (kt + 1 <= qt) cp_wait<1>(); else cp_wait<0>();
        __syncthreads();
        const int cur = kt & 1;
        const uint32_t* Kp = Ks + cur * 64 * AST;
        const uint32_t* Vp = Vs + cur * 64 * AST;

        if (kt == 0) {
            const uint32_t* qp = Qs + (warp * 16 + r4) * AST;
            #pragma unroll
            for (int p = 0; p < 4; p++) {
                qf[p][0] = h2scale(qp[p * 8 + c4], sc);
                qf[p][1] = h2scale(qp[8 * AST + p * 8 + c4], sc);
                qf[p][2] = h2scale(qp[p * 8 + c4 + 4], sc);
                qf[p][3] = h2scale(qp[8 * AST + p * 8 + c4 + 4], sc);
            }
        }

        // ---- S = Q K^T ----
        float sacc[8][4];
        #pragma unroll
        for (int nt = 0; nt < 8; nt++)
            #pragma unroll
            for (int r = 0; r < 4; r++) sacc[nt][r] = 0.f;

        #pragma unroll
        for (int p = 0; p < 4; p++) {
            #pragma unroll
            for (int nt = 0; nt < 8; nt++) {
                const uint32_t* kp = Kp + (nt * 8 + r4) * AST + p * 8;
                uint32_t bf[2];
                bf[0] = kp[c4];
                bf[1] = kp[c4 + 4];
                mma_f16(sacc[nt], qf[p], bf);
            }
        }

        // causal mask on diagonal tile
        if (kt == qt) {
            const int row0 = warp * 16 + r4;
            #pragma unroll
            for (int nt = 0; nt < 8; nt++) {
                const int cb = nt * 8 + 2 * c4;
                if (cb + 0 > row0)     sacc[nt][0] = -1e30f;
                if (cb + 1 > row0)     sacc[nt][1] = -1e30f;
                if (cb + 0 > row0 + 8) sacc[nt][2] = -1e30f;
                if (cb + 1 > row0 + 8) sacc[nt][3] = -1e30f;
            }
        }

        // ---- online softmax ----
        float rm0 = -1e30f, rm1 = -1e30f;
        #pragma unroll
        for (int nt = 0; nt < 8; nt++) {
            rm0 = fmaxf(rm0, fmaxf(sacc[nt][0], sacc[nt][1]));
            rm1 = fmaxf(rm1, fmaxf(sacc[nt][2], sacc[nt][3]));
        }
        rm0 = fmaxf(rm0, __shfl_xor_sync(~0u, rm0, 1));
        rm0 = fmaxf(rm0, __shfl_xor_sync(~0u, rm0, 2));
        rm1 = fmaxf(rm1, __shfl_xor_sync(~0u, rm1, 1));
        rm1 = fmaxf(rm1, __shfl_xor_sync(~0u, rm1, 2));

        const float mn0 = fmaxf(m0, rm0), mn1 = fmaxf(m1, rm1);
        const float f0 = __expf(m0 - mn0), f1 = __expf(m1 - mn1);
        m0 = mn0; m1 = mn1;

        float rs0 = 0.f, rs1 = 0.f;
        #pragma unroll
        for (int nt = 0; nt < 8; nt++) {
            float p0 = __expf(sacc[nt][0] - mn0);
            float p1 = __expf(sacc[nt][1] - mn0);
            float p2 = __expf(sacc[nt][2] - mn1);
            float p3 = __expf(sacc[nt][3] - mn1);
            rs0 += p0 + p1; rs1 += p2 + p3;
            __half2 w0 = __floats2half2_rn(p0, p1);
            __half2 w1 = __floats2half2_rn(p2, p3);
            Pw[r4 * AST + nt * 4 + c4]       = *(uint32_t*)&w0;
            Pw[(r4 + 8) * AST + nt * 4 + c4] = *(uint32_t*)&w1;
        }
        rs0 += __shfl_xor_sync(~0u, rs0, 1);
        rs0 += __shfl_xor_sync(~0u, rs0, 2);
        rs1 += __shfl_xor_sync(~0u, rs1, 1);
        rs1 += __shfl_xor_sync(~0u, rs1, 2);
        l0 = l0 * f0 + rs0;
        l1 = l1 * f1 + rs1;

        #pragma unroll
        for (int nt = 0; nt < 8; nt++) {
            oacc[nt][0] *= f0; oacc[nt][1] *= f0;
            oacc[nt][2] *= f1; oacc[nt][3] *= f1;
        }
        __syncwarp();

        // ---- O += P V ----
        #pragma unroll
        for (int p = 0; p < 4; p++) {
            uint32_t af[4];
            const uint32_t* pp  = Pw + r4 * AST + p * 8;
            const uint32_t* pp8 = Pw + (r4 + 8) * AST + p * 8;
            af[0] = pp[c4];
            af[1] = pp8[c4];
            af[2] = pp[c4 + 4];
            af[3] = pp8[c4 + 4];
            #pragma unroll
            for (int nt = 0; nt < 8; nt++) {
                const uint32_t* vp = Vp + (nt * 8 + r4) * AST + p * 8;
                uint32_t bf[2];
                bf[0] = vp[c4];
                bf[1] = vp[c4 + 4];
                mma_f16(oacc[nt], af, bf);
            }
        }

        __syncthreads();
        if (kt + 2 <= qt) { issue_kv(cur, (kt + 2) * 64); cp_commit(); }
    }

    // epilogue -> fp16 ctx [token][C]
    const float inv0 = 1.f / l0, inv1 = 1.f / l1;
    const int row0 = q0 + warp * 16 + r4;
    #pragma unroll
    for (int nt = 0; nt < 8; nt++) {
        const int col = h * HD + nt * 8 + 2 * c4;
        *(__half2*)(O + (size_t)(b * TD + row0) * CD + col) =
            __floats2half2_rn(oacc[nt][0] * inv0, oacc[nt][1] * inv0);
        *(__half2*)(O + (size_t)(b * TD + row0 + 8) * CD + col) =
            __floats2half2_rn(oacc[nt][2] * inv1, oacc[nt][3] * inv1);
    }
}

// ---------------------------------------------------------------------------
// Launch
// ---------------------------------------------------------------------------
extern "C" void kernel_launch(void* const* d_in, const int* in_sizes, int n_in,
                              void* d_out, int out_size)
{
    const float* x      = (const float*)d_in[0];
    const float* ln_a_g = (const float*)d_in[1];
    const float* ln_a_b = (const float*)d_in[2];
    const float* ln_b_g = (const float*)d_in[3];
    const float* ln_b_b = (const float*)d_in[4];
    const float* ln_c_g = (const float*)d_in[5];
    const float* ln_c_b = (const float*)d_in[6];
    const float* Wq = (const float*)d_in[7];  const float* bq = (const float*)d_in[8];
    const float* Wk = (const float*)d_in[9];  const float* bk = (const float*)d_in[10];
    const float* Wv = (const float*)d_in[11]; const float* bv = (const float*)d_in[12];
    const float* Wo = (const float*)d_in[13]; const float* bo = (const float*)d_in[14];
    const float* We = (const float*)d_in[15]; const float* be = (const float*)d_in[16];
    const float* Wd = (const float*)d_in[17]; const float* bd = (const float*)d_in[18];
    float* out = (float*)d_out;

    float *x2;
    __half *th, *t2h, *qh, *kh, *vt, *ctxh, *hh;
    __half2 *wqp, *wkp, *wvp, *wop, *wep, *wdp;
    cudaGetSymbolAddress((void**)&x2,   g_x2);
    cudaGetSymbolAddress((void**)&th,   g_th);
    cudaGetSymbolAddress((void**)&t2h,  g_t2h);
    cudaGetSymbolAddress((void**)&qh,   g_qh);
    cudaGetSymbolAddress((void**)&kh,   g_kh);
    cudaGetSymbolAddress((void**)&vt,   g_vt);
    cudaGetSymbolAddress((void**)&ctxh, g_ctxh);
    cudaGetSymbolAddress((void**)&hh,   g_hh);
    cudaGetSymbolAddress((void**)&wqp,  g_wqp);
    cudaGetSymbolAddress((void**)&wkp,  g_wkp);
    cudaGetSymbolAddress((void**)&wvp,  g_wvp);
    cudaGetSymbolAddress((void**)&wop,  g_wop);
    cudaGetSymbolAddress((void**)&wep,  g_wep);
    cudaGetSymbolAddress((void**)&wdp,  g_wdp);

    cudaFuncSetAttribute(attn_h, cudaFuncAttributeMaxDynamicSharedMemorySize,
                         ATTN_SMEM);
    cudaFuncSetAttribute(attn_h, cudaFuncAttributePreferredSharedMemoryCarveout,
                         100);

    // 0. weight conversion
    wconv<<<(CD/2)*CD/256,   256>>>(Wq, wqp, 10);
    wconv<<<(CD/2)*CD/256,   256>>>(Wk, wkp, 10);
    wconv<<<(CD/2)*CD/256,   256>>>(Wv, wvp, 10);
    wconv<<<(CD/2)*CD/256,   256>>>(Wo, wop, 10);
    wconv<<<(CD/2)*DFFD/256, 256>>>(We, wep, 12);
    wconv<<<(DFFD/2)*CD/256, 256>>>(Wd, wdp, 10);

    // 1. th = fp16(LN_b(LN_a(x)))
    ln2_kernel<<<NT, 256>>>(x, ln_a_g, ln_a_b, ln_b_g, ln_b_b, th);

    // 2. QKV (fused): q,k fp16 row-major; v fp16 transposed
    {
        dim3 grid(CD / 128, NT / 128, 3);
        gemm_h<<<grid, 256>>>(th, wqp, wkp, wvp, bq, bk, bv, nullptr,
                              nullptr, nullptr, nullptr,
                              qh, kh, vt, 1, NT, CD, CD, 0);
    }

    // 3. causal attention (fp16) -> ctxh
    {
        dim3 grid(TD / 64, BD * HN);
        attn_h<<<grid, 128, ATTN_SMEM>>>(qh, kh, vt, ctxh);
    }

    // 4. x2 = x + ctx @ Wo + bo
    {
        dim3 grid(CD / 128, NT / 128, 1);
        gemm_h<<<grid, 256>>>(ctxh, wop, wop, wop, bo, bo, bo, x,
                              x2, x2, x2, nullptr, nullptr, nullptr,
                              0, NT, CD, CD, 0);
    }

    // 5. t2h = fp16(LN_c(x2))
    ln1_kernel<<<NT, 256>>>(x2, ln_c_g, ln_c_b, t2h);

    // 6. hh = fp16(silu(t2 @ We + be))
    {
        dim3 grid(DFFD / 128, NT / 128, 1);
        gemm_h<<<grid, 256>>>(t2h, wep, wep, wep, be, be, be, nullptr,
                              nullptr, nullptr, nullptr, hh, hh, hh,
                              0, NT, DFFD, CD, 1);
    }

    // 7. out = x2 + h @ Wd + bd
    {
        dim3 grid(CD / 128, NT / 128, 1);
        gemm_h<<<grid, 256>>>(hh, wdp, wdp, wdp, bd, bd, bd, x2,
                              out, out, out, nullptr, nullptr, nullptr,
                              0, NT, CD, DFFD, 0);
    }
}

// round 10
// speedup vs baseline: 2.2594x; 1.0075x over previous
#include <cuda_runtime.h>
#include <cuda_fp16.h>
#include <math.h>
#include <stdint.h>

// Problem dims
#define BD   2
#define TD   2048
#define CD   1024
#define HN   16
#define HD   64
#define DFFD 4096
#define NT   (BD * TD)   // 4096 tokens

// ---------------------------------------------------------------------------
// Scratch (device globals)
// ---------------------------------------------------------------------------
__device__ float  g_x2 [(size_t)NT * CD];
__device__ __half g_th  [(size_t)NT * CD];
__device__ __half g_t2h [(size_t)NT * CD];
__device__ __half g_qh  [(size_t)NT * CD];
__device__ __half g_kh  [(size_t)NT * CD];
__device__ __half g_vt  [(size_t)CD * NT];    // V transposed [dim][token]
__device__ __half g_ctxh[(size_t)NT * CD];
__device__ __half g_hh  [(size_t)NT * DFFD];
// k-pair-packed fp16 weights
__device__ __half2 g_wqp[(CD/2) * CD];
__device__ __half2 g_wkp[(CD/2) * CD];
__device__ __half2 g_wvp[(CD/2) * CD];
__device__ __half2 g_wop[(CD/2) * CD];
__device__ __half2 g_wep[(CD/2) * DFFD];
__device__ __half2 g_wdp[(DFFD/2) * CD];

// ---------------------------------------------------------------------------
// Helpers
// ---------------------------------------------------------------------------
__device__ __forceinline__ void cp16(uint32_t smem_dst, const void* gptr) {
    asm volatile("cp.async.cg.shared.global [%0], [%1], 16;\n"
                 :: "r"(smem_dst), "l"(gptr));
}
__device__ __forceinline__ void cp_commit() {
    asm volatile("cp.async.commit_group;\n" ::: "memory");
}
template <int N>
__device__ __forceinline__ void cp_wait() {
    asm volatile("cp.async.wait_group %0;\n" :: "n"(N) : "memory");
}
__device__ __forceinline__ void mma_f16(float* c, const uint32_t* a, const uint32_t* b) {
    asm volatile(
        "mma.sync.aligned.m16n8k16.row.col.f32.f16.f16.f32 "
        "{%0,%1,%2,%3},{%4,%5,%6,%7},{%8,%9},{%0,%1,%2,%3};"
        : "+f"(c[0]), "+f"(c[1]), "+f"(c[2]), "+f"(c[3])
        : "r"(a[0]), "r"(a[1]), "r"(a[2]), "r"(a[3]), "r"(b[0]), "r"(b[1]));
}
__device__ __forceinline__ void ldsm4(uint32_t* r, uint32_t addr) {
    asm volatile(
        "ldmatrix.sync.aligned.m8n8.x4.shared.b16 {%0,%1,%2,%3}, [%4];"
        : "=r"(r[0]), "=r"(r[1]), "=r"(r[2]), "=r"(r[3]) : "r"(addr));
}
__device__ __forceinline__ uint32_t h2scale(uint32_t w, __half2 s) {
    __half2 a = *(__half2*)&w;
    a = __hmul2(a, s);
    return *(uint32_t*)&a;
}

// ---------------------------------------------------------------------------
// Fused weight conversion: all 6 matrices in one launch.
// Layout jobs: [q|k|v|o] 4 x 2^19 words (nshift=10), then We 2^21 (nshift=12),
// then Wd 2^21 (nshift=10).
// ---------------------------------------------------------------------------
__global__ __launch_bounds__(256) void wconv_all(
    const float* __restrict__ Wq, const float* __restrict__ Wk,
    const float* __restrict__ Wv, const float* __restrict__ Wo,
    const float* __restrict__ We, const float* __restrict__ Wd,
    __half2* __restrict__ oq, __half2* __restrict__ ok,
    __half2* __restrict__ ov, __half2* __restrict__ oo,
    __half2* __restrict__ oe, __half2* __restrict__ od)
{
    int idx = blockIdx.x * 256 + threadIdx.x;
    const float* W;
    __half2* out;
    int nshift, i;
    if (idx < (1 << 21)) {                       // q,k,v,o
        const int m = idx >> 19;
        i = idx & ((1 << 19) - 1);
        W   = (m == 0) ? Wq : (m == 1) ? Wk : (m == 2) ? Wv : Wo;
        out = (m == 0) ? oq : (m == 1) ? ok : (m == 2) ? ov : oo;
        nshift = 10;
    } else if (idx < (2 << 21)) {                // We
        i = idx - (1 << 21);
        W = We; out = oe; nshift = 12;
    } else {                                     // Wd
        i = idx - (2 << 21);
        W = Wd; out = od; nshift = 10;
    }
    const int kk = i >> nshift;
    const int n  = i & ((1 << nshift) - 1);
    const size_t base = ((size_t)(2 * kk) << nshift) + n;
    out[i] = __floats2half2_rn(W[base], W[base + ((size_t)1 << nshift)]);
}

// ---------------------------------------------------------------------------
// Fused double LayerNorm -> fp16 out
// ---------------------------------------------------------------------------
__global__ __launch_bounds__(256) void ln2_kernel(
    const float* __restrict__ x,
    const float* __restrict__ ga, const float* __restrict__ ba,
    const float* __restrict__ gb, const float* __restrict__ bb,
    __half* __restrict__ out)
{
    __shared__ float red[16];
    __shared__ float bc[2];
    const int row = blockIdx.x, tid = threadIdx.x;
    const float4 v = *(const float4*)(x + (size_t)row * CD + tid * 4);

    float s  = v.x + v.y + v.z + v.w;
    float s2 = v.x*v.x + v.y*v.y + v.z*v.z + v.w*v.w;
    #pragma unroll
    for (int o = 16; o; o >>= 1) {
        s  += __shfl_xor_sync(~0u, s,  o);
        s2 += __shfl_xor_sync(~0u, s2, o);
    }
    if ((tid & 31) == 0) { red[(tid >> 5)*2] = s; red[(tid >> 5)*2 + 1] = s2; }
    __syncthreads();
    if (tid == 0) {
        float a = 0.f, b2 = 0.f;
        #pragma unroll
        for (int w = 0; w < 8; w++) { a += red[w*2]; b2 += red[w*2 + 1]; }
        float mu  = a * (1.f / CD);
        float var = b2 * (1.f / CD) - mu * mu;
        bc[0] = mu; bc[1] = rsqrtf(var + 1e-5f);
    }
    __syncthreads();
    float mu = bc[0], rstd = bc[1];
    __syncthreads();

    const float4 g4 = *(const float4*)(ga + tid * 4);
    const float4 b4 = *(const float4*)(ba + tid * 4);
    float y[4];
    y[0] = (v.x - mu) * rstd * g4.x + b4.x;
    y[1] = (v.y - mu) * rstd * g4.y + b4.y;
    y[2] = (v.z - mu) * rstd * g4.z + b4.z;
    y[3] = (v.w - mu) * rstd * g4.w + b4.w;

    s  = y[0] + y[1] + y[2] + y[3];
    s2 = y[0]*y[0] + y[1]*y[1] + y[2]*y[2] + y[3]*y[3];
    #pragma unroll
    for (int o = 16; o; o >>= 1) {
        s  += __shfl_xor_sync(~0u, s,  o);
        s2 += __shfl_xor_sync(~0u, s2, o);
    }
    if ((tid & 31) == 0) { red[(tid >> 5)*2] = s; red[(tid >> 5)*2 + 1] = s2; }
    __syncthreads();
    if (tid == 0) {
        float a = 0.f, b2 = 0.f;
        #pragma unroll
        for (int w = 0; w < 8; w++) { a += red[w*2]; b2 += red[w*2 + 1]; }
        float mu2  = a * (1.f / CD);
        float var2 = b2 * (1.f / CD) - mu2 * mu2;
        bc[0] = mu2; bc[1] = rsqrtf(var2 + 1e-5f);
    }
    __syncthreads();
    mu = bc[0]; rstd = bc[1];

    const float4 g24 = *(const float4*)(gb + tid * 4);
    const float4 b24 = *(const float4*)(bb + tid * 4);
    float o0 = (y[0] - mu) * rstd * g24.x + b24.x;
    float o1 = (y[1] - mu) * rstd * g24.y + b24.y;
    float o2 = (y[2] - mu) * rstd * g24.z + b24.z;
    float o3 = (y[3] - mu) * rstd * g24.w + b24.w;
    __half* op = out + (size_t)row * CD + tid * 4;
    *(__half2*)(op)     = __floats2half2_rn(o0, o1);
    *(__half2*)(op + 2) = __floats2half2_rn(o2, o3);
}

__global__ __launch_bounds__(256) void ln1_kernel(
    const float* __restrict__ x,
    const float* __restrict__ g, const float* __restrict__ b,
    __half* __restrict__ out)
{
    __shared__ float red[16];
    __shared__ float bc[2];
    const int row = blockIdx.x, tid = threadIdx.x;
    const float4 v = *(const float4*)(x + (size_t)row * CD + tid * 4);

    float s  = v.x + v.y + v.z + v.w;
    float s2 = v.x*v.x + v.y*v.y + v.z*v.z + v.w*v.w;
    #pragma unroll
    for (int o = 16; o; o >>= 1) {
        s  += __shfl_xor_sync(~0u, s,  o);
        s2 += __shfl_xor_sync(~0u, s2, o);
    }
    if ((tid & 31) == 0) { red[(tid >> 5)*2] = s; red[(tid >> 5)*2 + 1] = s2; }
    __syncthreads();
    if (tid == 0) {
        float a = 0.f, b2 = 0.f;
        #pragma unroll
        for (int w = 0; w < 8; w++) { a += red[w*2]; b2 += red[w*2 + 1]; }
        float mu  = a * (1.f / CD);
        float var = b2 * (1.f / CD) - mu * mu;
        bc[0] = mu; bc[1] = rsqrtf(var + 1e-5f);
    }
    __syncthreads();
    const float mu = bc[0], rstd = bc[1];
    const float4 g4 = *(const float4*)(g + tid * 4);
    const float4 b4 = *(const float4*)(b + tid * 4);
    float o0 = (v.x - mu) * rstd * g4.x + b4.x;
    float o1 = (v.y - mu) * rstd * g4.y + b4.y;
    float o2 = (v.z - mu) * rstd * g4.z + b4.z;
    float o3 = (v.w - mu) * rstd * g4.w + b4.w;
    __half* op = out + (size_t)row * CD + tid * 4;
    *(__half2*)(op)     = __floats2half2_rn(o0, o1);
    *(__half2*)(op + 2) = __floats2half2_rn(o2, o3);
}

// ---------------------------------------------------------------------------
// FP16 tensor-core GEMM with ldmatrix A-fragments.
// 128x128 tile, BK=32, 2-stage, 8 warps (2x4), warp 64x32.
//   A smem: [m][word] stride 20 words (rows conflict-free for LDSM: 20m mod 32
//           cycles through 8 disjoint 4-bank groups).
//   B smem: [kk][n'] n' = n ^ (8*kk)  (k-pair packed; word == B-fragment reg).
// ---------------------------------------------------------------------------
__global__ __launch_bounds__(256, 2) void gemm_h(
    const __half* __restrict__ A,
    const __half2* __restrict__ Wp0, const __half2* __restrict__ Wp1,
    const __half2* __restrict__ Wp2,
    const float* __restrict__ b0, const float* __restrict__ b1,
    const float* __restrict__ b2,
    const float* __restrict__ res,
    float* __restrict__ C0, float* __restrict__ C1, float* __restrict__ C2,
    __half* __restrict__ H0, __half* __restrict__ H1, __half* __restrict__ H2,
    int vtz2, int M, int N, int K, int act)
{
    __shared__ uint32_t As[2][128 * 20];
    __shared__ uint32_t Bs[2][16 * 128];

    const int z = blockIdx.z;
    const __half2* Wp  = (z == 0) ? Wp0 : (z == 1) ? Wp1 : Wp2;
    const float*  bias = (z == 0) ? b0  : (z == 1) ? b1  : b2;
    float*        Cc   = (z == 0) ? C0  : (z == 1) ? C1  : C2;
    __half*       Hh   = (z == 0) ? H0  : (z == 1) ? H1  : H2;
    const bool    vt   = (z == 2) && vtz2;

    const int tid  = threadIdx.x;
    const int lane = tid & 31;
    const int warp = tid >> 5;
    const int wm = warp & 1;
    const int wn = warp >> 1;
    const int bm = blockIdx.y * 128;
    const int bn = blockIdx.x * 128;

    const int ar1 = tid >> 2,          aq1 = tid & 3;
    const int ar2 = (tid + 256) >> 2,  aq2 = (tid + 256) & 3;
    const int bk1 = tid >> 5,          bn1 = tid & 31;
    const int bk2 = (tid + 256) >> 5,  bn2 = (tid + 256) & 31;

    const uint32_t sA = (uint32_t)__cvta_generic_to_shared(&As[0][0]);
    const uint32_t sB = (uint32_t)__cvta_generic_to_shared(&Bs[0][0]);
    const uint32_t aD1 = sA + (uint32_t)(ar1 * 20 + aq1 * 4) * 4u;
    const uint32_t aD2 = sA + (uint32_t)(ar2 * 20 + aq2 * 4) * 4u;
    const uint32_t bD1 = sB + (uint32_t)(bk1 * 128 + ((bn1 * 4) ^ (8 * bk1))) * 4u;
    const uint32_t bD2 = sB + (uint32_t)(bk2 * 128 + ((bn2 * 4) ^ (8 * bk2))) * 4u;

    const __half*  gA1 = A + (size_t)(bm + ar1) * K + aq1 * 8;
    const __half*  gA2 = A + (size_t)(bm + ar2) * K + aq2 * 8;
    const __half2* gB1 = Wp + (size_t)bk1 * N + bn + bn1 * 4;
    const __half2* gB2 = Wp + (size_t)bk2 * N + bn + bn2 * 4;
    const size_t bStep = (size_t)16 * N;

    // ldmatrix per-thread A addresses: lane -> (matrix mi, row rr)
    const int mi = lane >> 3;     // 0..3
    const int rr = lane & 7;
    uint32_t aL[4];
    #pragma unroll
    for (int mf = 0; mf < 4; mf++) {
        const int m = wm * 64 + mf * 16 + (mi & 1) * 8 + rr;
        aL[mf] = sA + (uint32_t)(m * 20 + (mi >> 1) * 4) * 4u;
    }

    float acc[4][4][4];
    #pragma unroll
    for (int i = 0; i < 4; i++)
        #pragma unroll
        for (int j = 0; j < 4; j++)
            #pragma unroll
            for (int r = 0; r < 4; r++) acc[i][j][r] = 0.f;

    auto issue = [&](uint32_t so) {
        cp16(aD1 + so * 10240u, gA1);
        cp16(aD2 + so * 10240u, gA2);
        cp16(bD1 + so * 8192u,  gB1);
        cp16(bD2 + so * 8192u,  gB2);
        gA1 += 32; gA2 += 32; gB1 += bStep; gB2 += bStep;
    };

    issue(0); cp_commit();
    issue(1); cp_commit();

    const int nK = K >> 5;
    const int r4 = lane >> 2;
    const int c4 = lane & 3;
    const int nb0 = wn * 32 + r4;

    for (int kt = 0; kt < nK; kt++) {
        cp_wait<1>();
        __syncthreads();
        const int cur = kt & 1;
        const uint32_t curA = (uint32_t)cur * 10240u;
        const uint32_t* Bp = &Bs[cur][0];

        #pragma unroll
        for (int p = 0; p < 2; p++) {
            uint32_t af[4][4], bf[4][2];
            #pragma unroll
            for (int mf = 0; mf < 4; mf++)
                ldsm4(af[mf], aL[mf] + curA + (uint32_t)(p * 32));
            #pragma unroll
            for (int nf = 0; nf < 4; nf++) {
                const int n = nb0 + nf * 8;
                bf[nf][0] = Bp[(p * 8 + c4) * 128     + (n ^ (64 * p + 8 * c4))];
                bf[nf][1] = Bp[(p * 8 + c4 + 4) * 128 + (n ^ (64 * p + 8 * c4 + 32))];
            }
            #pragma unroll
            for (int mf = 0; mf < 4; mf++)
                #pragma unroll
                for (int nf = 0; nf < 4; nf++)
                    mma_f16(acc[mf][nf], af[mf], bf[nf]);
        }
        __syncthreads();
        if (kt + 2 < nK) issue(cur);
        cp_commit();
    }

    // epilogue
    #pragma unroll
    for (int mf = 0; mf < 4; mf++) {
        #pragma unroll
        for (int nf = 0; nf < 4; nf++) {
            const int col = bn + wn * 32 + nf * 8 + c4 * 2;
            const float bx = bias[col], by = bias[col + 1];
            #pragma unroll
            for (int h = 0; h < 2; h++) {
                const int row = bm + wm * 64 + mf * 16 + r4 + h * 8;
                float ox = acc[mf][nf][h * 2 + 0] + bx;
                float oy = acc[mf][nf][h * 2 + 1] + by;
                if (act) {
                    ox *= 1.f / (1.f + __expf(-ox));
                    oy *= 1.f / (1.f + __expf(-oy));
                }
                const size_t off = (size_t)row * N + col;
                if (res) {
                    const float2 rr2 = *(const float2*)(res + off);
                    ox += rr2.x; oy += rr2.y;
                }
                if (Cc) {
                    float2 o; o.x = ox; o.y = oy;
                    *(float2*)(Cc + off) = o;
                }
                if (Hh) {
                    if (vt) {
                        Hh[(size_t)col * M + row]       = __float2half(ox);
                        Hh[(size_t)(col + 1) * M + row] = __float2half(oy);
                    } else {
                        *(__half2*)(Hh + off) = __floats2half2_rn(ox, oy);
                    }
                }
            }
        }
    }
}

// ---------------------------------------------------------------------------
// FP16 flash attention (unchanged from R9)
// ---------------------------------------------------------------------------
#define AST 36
#define ATTN_SMEM ((64*AST + 2*64*AST + 2*64*AST + 4*16*AST) * 4)

__global__ __launch_bounds__(128) void attn_h(
    const __half* __restrict__ Qh, const __half* __restrict__ Kh,
    const __half* __restrict__ Vt, __half* __restrict__ O)
{
    extern __shared__ uint32_t sm[];
    uint32_t* Qs = sm;
    uint32_t* Ks = Qs + 64 * AST;
    uint32_t* Vs = Ks + 2 * 64 * AST;
    uint32_t* Ps = Vs + 2 * 64 * AST;

    const int bh = blockIdx.y;
    const int b = bh >> 4, h = bh & 15;
    const int qt = blockIdx.x;
    const int q0 = qt * 64;
    const int tid = threadIdx.x;
    const int lane = tid & 31;
    const int warp = tid >> 5;
    const int r4 = lane >> 2;
    const int c4 = lane & 3;

    const __half* qg = Qh + (size_t)(b * TD + q0) * CD + h * HD;
    const __half* kg = Kh + (size_t)b * TD * CD + h * HD;
    const __half* vg = Vt + (size_t)(h * HD) * NT + b * TD;

    const uint32_t sQ = (uint32_t)__cvta_generic_to_shared(Qs);
    const uint32_t sK = (uint32_t)__cvta_generic_to_shared(Ks);
    const uint32_t sV = (uint32_t)__cvta_generic_to_shared(Vs);

    #pragma unroll
    for (int i = 0; i < 4; i++) {
        const int idx = tid + i * 128;
        const int row = idx >> 3, cc = idx & 7;
        cp16(sQ + (uint32_t)(row * AST + cc * 4) * 4u, qg + row * CD + cc * 8);
    }
    auto issue_kv = [&](int buf, int k0) {
        #pragma unroll
        for (int i = 0; i < 4; i++) {
            const int idx = tid + i * 128;
            const int row = idx >> 3, cc = idx & 7;
            cp16(sK + (uint32_t)(buf * 64 * AST + row * AST + cc * 4) * 4u,
                 kg + (size_t)(k0 + row) * CD + cc * 8);
            cp16(sV + (uint32_t)(buf * 64 * AST + row * AST + cc * 4) * 4u,
                 vg + (size_t)row * NT + k0 + cc * 8);
        }
    };
    issue_kv(0, 0);
    cp_commit();
    if (qt >= 1) { issue_kv(1, 64); cp_commit(); }

    uint32_t qf[4][4];
    float oacc[8][4];
    #pragma unroll
    for (int nt = 0; nt < 8; nt++)
        #pragma unroll
        for (int r = 0; r < 4; r++) oacc[nt][r] = 0.f;
    float m0 = -1e30f, m1 = -1e30f, l0 = 0.f, l1 = 0.f;

    uint32_t* Pw = Ps + warp * 16 * AST;
    const __half2 sc = __float2half2_rn(0.125f);

    for (int kt = 0; kt <= qt; kt++) {
        if (kt + 1 <= qt) cp_wait<1>(); else cp_wait<0>();
        __syncthreads();
        const int cur = kt & 1;
        const uint32_t* Kp = Ks + cur * 64 * AST;
        const uint32_t* Vp = Vs + cur * 64 * AST;

        if (kt == 0) {
            const uint32_t* qp = Qs + (warp * 16 + r4) * AST;
            #pragma unroll
            for (int p = 0; p < 4; p++) {
                qf[p][0] = h2scale(qp[p * 8 + c4], sc);
                qf[p][1] = h2scale(qp[8 * AST + p * 8 + c4], sc);
                qf[p][2] = h2scale(qp[p * 8 + c4 + 4], sc);
                qf[p][3] = h2scale(qp[8 * AST + p * 8 + c4 + 4], sc);
            }
        }

        float sacc[8][4];
        #pragma unroll
        for (int nt = 0; nt < 8; nt++)
            #pragma unroll
            for (int r = 0; r < 4; r++) sacc[nt][r] = 0.f;

        #pragma unroll
        for (int p = 0; p < 4; p++) {
            #pragma unroll
            for (int nt = 0; nt < 8; nt++) {
                const uint32_t* kp = Kp + (nt * 8 + r4) * AST + p * 8;
                uint32_t bf[2];
                bf[0] = kp[c4];
                bf[1] = kp[c4 + 4];
                mma_f16(sacc[nt], qf[p], bf);
            }
        }

        if (kt == qt) {
            const int row0 = warp * 16 + r4;
            #pragma unroll
            for (int nt = 0; nt < 8; nt++) {
                const int cb = nt * 8 + 2 * c4;
                if (cb + 0 > row0)     sacc[nt][0] = -1e30f;
                if (cb + 1 > row0)     sacc[nt][1] = -1e30f;
                if (cb + 0 > row0 + 8) sacc[nt][2] = -1e30f;
                if (cb + 1 > row0 + 8) sacc[nt][3] = -1e30f;
            }
        }

        float rm0 = -1e30f, rm1 = -1e30f;
        #pragma unroll
        for (int nt = 0; nt < 8; nt++) {
            rm0 = fmaxf(rm0, fmaxf(sacc[nt][0], sacc[nt][1]));
            rm1 = fmaxf(rm1, fmaxf(sacc[nt][2], sacc[nt][3]));
        }
        rm0 = fmaxf(rm0, __shfl_xor_sync(~0u, rm0, 1));
        rm0 = fmaxf(rm0, __shfl_xor_sync(~0u, rm0, 2));
        rm1 = fmaxf(rm1, __shfl_xor_sync(~0u, rm1, 1));
        rm1 = fmaxf(rm1, __shfl_xor_sync(~0u, rm1, 2));

        const float mn0 = fmaxf(m0, rm0), mn1 = fmaxf(m1, rm1);
        const float f0 = __expf(m0 - mn0), f1 = __expf(m1 - mn1);
        m0 = mn0; m1 = mn1;

        float rs0 = 0.f, rs1 = 0.f;
        #pragma unroll
        for (int nt = 0; nt < 8; nt++) {
            float p0 = __expf(sacc[nt][0] - mn0);
            float p1 = __expf(sacc[nt][1] - mn0);
            float p2 = __expf(sacc[nt][2] - mn1);
            float p3 = __expf(sacc[nt][3] - mn1);
            rs0 += p0 + p1; rs1 += p2 + p3;
            __half2 w0 = __floats2half2_rn(p0, p1);
            __half2 w1 = __floats2half2_rn(p2, p3);
            Pw[r4 * AST + nt * 4 + c4]       = *(uint32_t*)&w0;
            Pw[(r4 + 8) * AST + nt * 4 + c4] = *(uint32_t*)&w1;
        }
        rs0 += __shfl_xor_sync(~0u, rs0, 1);
        rs0 += __shfl_xor_sync(~0u, rs0, 2);
        rs1 += __shfl_xor_sync(~0u, rs1, 1);
        rs1 += __shfl_xor_sync(~0u, rs1, 2);
        l0 = l0 * f0 + rs0;
        l1 = l1 * f1 + rs1;

        #pragma unroll
        for (int nt = 0; nt < 8; nt++) {
            oacc[nt][0] *= f0; oacc[nt][1] *= f0;
            oacc[nt][2] *= f1; oacc[nt][3] *= f1;
        }
        __syncwarp();

        #pragma unroll
        for (int p = 0; p < 4; p++) {
            uint32_t af[4];
            const uint32_t* pp  = Pw + r4 * AST + p * 8;
            const uint32_t* pp8 = Pw + (r4 + 8) * AST + p * 8;
            af[0] = pp[c4];
            af[1] = pp8[c4];
            af[2] = pp[c4 + 4];
            af[3] = pp8[c4 + 4];
            #pragma unroll
            for (int nt = 0; nt < 8; nt++) {
                const uint32_t* vp = Vp + (nt * 8 + r4) * AST + p * 8;
                uint32_t bf[2];
                bf[0] = vp[c4];
                bf[1] = vp[c4 + 4];
                mma_f16(oacc[nt], af, bf);
            }
        }

        __syncthreads();
        if (kt + 2 <= qt) { issue_kv(cur, (kt + 2) * 64); cp_commit(); }
    }

    const float inv0 = 1.f / l0, inv1 = 1.f / l1;
    const int row0 = q0 + warp * 16 + r4;
    #pragma unroll
    for (int nt = 0; nt < 8; nt++) {
        const int col = h * HD + nt * 8 + 2 * c4;
        *(__half2*)(O + (size_t)(b * TD + row0) * CD + col) =
            __floats2half2_rn(oacc[nt][0] * inv0, oacc[nt][1] * inv0);
        *(__half2*)(O + (size_t)(b * TD + row0 + 8) * CD + col) =
            __floats2half2_rn(oacc[nt][2] * inv1, oacc[nt][3] * inv1);
    }
}

// ---------------------------------------------------------------------------
// Launch
// ---------------------------------------------------------------------------
extern "C" void kernel_launch(void* const* d_in, const int* in_sizes, int n_in,
                              void* d_out, int out_size)
{
    const float* x      = (const float*)d_in[0];
    const float* ln_a_g = (const float*)d_in[1];
    const float* ln_a_b = (const float*)d_in[2];
    const float* ln_b_g = (const float*)d_in[3];
    const float* ln_b_b = (const float*)d_in[4];
    const float* ln_c_g = (const float*)d_in[5];
    const float* ln_c_b = (const float*)d_in[6];
    const float* Wq = (const float*)d_in[7];  const float* bq = (const float*)d_in[8];
    const float* Wk = (const float*)d_in[9];  const float* bk = (const float*)d_in[10];
    const float* Wv = (const float*)d_in[11]; const float* bv = (const float*)d_in[12];
    const float* Wo = (const float*)d_in[13]; const float* bo = (const float*)d_in[14];
    const float* We = (const float*)d_in[15]; const float* be = (const float*)d_in[16];
    const float* Wd = (const float*)d_in[17]; const float* bd = (const float*)d_in[18];
    float* out = (float*)d_out;

    float *x2;
    __half *th, *t2h, *qh, *kh, *vt, *ctxh, *hh;
    __half2 *wqp, *wkp, *wvp, *wop, *wep, *wdp;
    cudaGetSymbolAddress((void**)&x2,   g_x2);
    cudaGetSymbolAddress((void**)&th,   g_th);
    cudaGetSymbolAddress((void**)&t2h,  g_t2h);
    cudaGetSymbolAddress((void**)&qh,   g_qh);
    cudaGetSymbolAddress((void**)&kh,   g_kh);
    cudaGetSymbolAddress((void**)&vt,   g_vt);
    cudaGetSymbolAddress((void**)&ctxh, g_ctxh);
    cudaGetSymbolAddress((void**)&hh,   g_hh);
    cudaGetSymbolAddress((void**)&wqp,  g_wqp);
    cudaGetSymbolAddress((void**)&wkp,  g_wkp);
    cudaGetSymbolAddress((void**)&wvp,  g_wvp);
    cudaGetSymbolAddress((void**)&wop,  g_wop);
    cudaGetSymbolAddress((void**)&wep,  g_wep);
    cudaGetSymbolAddress((void**)&wdp,  g_wdp);

    cudaFuncSetAttribute(attn_h, cudaFuncAttributeMaxDynamicSharedMemorySize,
                         ATTN_SMEM);
    cudaFuncSetAttribute(attn_h, cudaFuncAttributePreferredSharedMemoryCarveout,
                         100);

    // 0. fused weight conversion (6 matrices, one launch)
    {
        const int total = (1 << 21) + (1 << 21) + (1 << 21);  // 4x2^19 + 2^21 + 2^21
        wconv_all<<<total / 256, 256>>>(Wq, Wk, Wv, Wo, We, Wd,
                                        wqp, wkp, wvp, wop, wep, wdp);
    }

    // 1. th = fp16(LN_b(LN_a(x)))
    ln2_kernel<<<NT, 256>>>(x, ln_a_g, ln_a_b, ln_b_g, ln_b_b, th);

    // 2. QKV (fused): q,k fp16 row-major; v fp16 transposed
    {
        dim3 grid(CD / 128, NT / 128, 3);
        gemm_h<<<grid, 256>>>(th, wqp, wkp, wvp, bq, bk, bv, nullptr,
                              nullptr, nullptr, nullptr,
                              qh, kh, vt, 1, NT, CD, CD, 0);
    }

    // 3. causal attention (fp16) -> ctxh
    {
        dim3 grid(TD / 64, BD * HN);
        attn_h<<<grid, 128, ATTN_SMEM>>>(qh, kh, vt, ctxh);
    }

    // 4. x2 = x + ctx @ Wo + bo
    {
        dim3 grid(CD / 128, NT / 128, 1);
        gemm_h<<<grid, 256>>>(ctxh, wop, wop, wop, bo, bo, bo, x,
                              x2, x2, x2, nullptr, nullptr, nullptr,
                              0, NT, CD, CD, 0);
    }

    // 5. t2h = fp16(LN_c(x2))
    ln1_kernel<<<NT, 256>>>(x2, ln_c_g, ln_c_b, t2h);

    // 6. hh = fp16(silu(t2 @ We + be))
    {
        dim3 grid(DFFD / 128, NT / 128, 1);
        gemm_h<<<grid, 256>>>(t2h, wep, wep, wep, be, be, be, nullptr,
                              nullptr, nullptr, nullptr, hh, hh, hh,
                              0, NT, DFFD, CD, 1);
    }

    // 7. out = x2 + h @ Wd + bd
    {
        dim3 grid(CD / 128, NT / 128, 1);
        gemm_h<<<grid, 256>>>(hh, wdp, wdp, wdp, bd, bd, bd, x2,
                              out, out, out, nullptr, nullptr, nullptr,
                              0, NT, CD, DFFD, 0);
    }
}